// round 12
// baseline (speedup 1.0000x reference)
#include <cuda_runtime.h>
#include <cuda_fp16.h>
#include <mma.h>
#include <cstdint>

using namespace nvcuda;

#define BB   4
#define HH   8
#define LL   2048
#define CC   512
#define DD   64

// fp16 scratch (allocation-free rule: __device__ globals)
__device__ __half g_q[BB*HH*LL*DD];
__device__ __half g_k[BB*HH*LL*DD];
__device__ __half g_v[BB*HH*LL*DD];
__device__ __half g_ctx[(size_t)BB*LL*CC];
__device__ __half g_ppgh[(size_t)BB*CC*LL];
__device__ __half g_ecgh[(size_t)BB*CC*LL];
__device__ __half g_wh[4*CC*CC];     // Wq | Wk | Wv | Wo

__device__ __forceinline__ uint2 f4_to_h2x2(float4 v) {
    __half2 a = __floats2half2_rn(v.x, v.y);
    __half2 b = __floats2half2_rn(v.z, v.w);
    uint2 r;
    r.x = *(unsigned int*)&a;
    r.y = *(unsigned int*)&b;
    return r;
}

// exp(s*0.125) via MUFU: ex2.approx(s * 0.125*log2(e)). rel err ~2^-22.
__device__ __forceinline__ float ex2_fast(float x) {
    float y;
    asm("ex2.approx.f32 %0, %1;" : "=f"(y) : "f"(x));
    return y;
}
#define EXP8_SCALE 0.18033688011f

// ---- PTX wrappers -----------------------------------------------------------
__device__ __forceinline__ unsigned smem_u32(const void* p) {
    return (unsigned)__cvta_generic_to_shared(p);
}
__device__ __forceinline__ void ldm_x4(unsigned& r0, unsigned& r1, unsigned& r2,
                                       unsigned& r3, unsigned addr) {
    asm volatile("ldmatrix.sync.aligned.m8n8.x4.shared.b16 {%0,%1,%2,%3}, [%4];"
                 : "=r"(r0), "=r"(r1), "=r"(r2), "=r"(r3) : "r"(addr));
}
__device__ __forceinline__ void ldm_x4_t(unsigned& r0, unsigned& r1, unsigned& r2,
                                         unsigned& r3, unsigned addr) {
    asm volatile("ldmatrix.sync.aligned.m8n8.x4.trans.shared.b16 {%0,%1,%2,%3}, [%4];"
                 : "=r"(r0), "=r"(r1), "=r"(r2), "=r"(r3) : "r"(addr));
}
__device__ __forceinline__ void mma16816_h(unsigned& c0, unsigned& c1,
                                           unsigned a0, unsigned a1, unsigned a2,
                                           unsigned a3, unsigned b0, unsigned b1) {
    asm volatile("mma.sync.aligned.m16n8k16.row.col.f16.f16.f16.f16 "
                 "{%0,%1}, {%2,%3,%4,%5}, {%6,%7}, {%0,%1};"
                 : "+r"(c0), "+r"(c1)
                 : "r"(a0), "r"(a1), "r"(a2), "r"(a3), "r"(b0), "r"(b1));
}
__device__ __forceinline__ void mma16816_f(float& d0, float& d1, float& d2, float& d3,
                                           unsigned a0, unsigned a1, unsigned a2,
                                           unsigned a3, unsigned b0, unsigned b1) {
    asm volatile("mma.sync.aligned.m16n8k16.row.col.f32.f16.f16.f32 "
                 "{%0,%1,%2,%3}, {%4,%5,%6,%7}, {%8,%9}, {%0,%1,%2,%3};"
                 : "+f"(d0), "+f"(d1), "+f"(d2), "+f"(d3)
                 : "r"(a0), "r"(a1), "r"(a2), "r"(a3), "r"(b0), "r"(b1));
}
__device__ __forceinline__ void cp_async16(unsigned dst, const void* src) {
    asm volatile("cp.async.ca.shared.global [%0], [%1], 16;"
                 :: "r"(dst), "l"(src));
}
__device__ __forceinline__ void cp_commit() {
    asm volatile("cp.async.commit_group;");
}
__device__ __forceinline__ void cp_wait0() {
    asm volatile("cp.async.wait_group 0;");
}

// ---------------------------------------------------------------------------
// One fused fp32->fp16 conversion for all 6 tensors.
// ---------------------------------------------------------------------------
#define NX4 (BB*CC*LL/4)
#define NW4 (CC*CC/4)
__global__ void cvt_all(const float* __restrict__ ppg, const float* __restrict__ ecg,
                        const float* __restrict__ Wq, const float* __restrict__ Wk,
                        const float* __restrict__ Wv, const float* __restrict__ Wo,
                        __half* __restrict__ ppgh, __half* __restrict__ ecgh,
                        __half* __restrict__ wh) {
    int i = blockIdx.x * blockDim.x + threadIdx.x;
    const float* src;
    __half* dst;
    int off;
    if (i < NX4)                    { src = ppg; dst = ppgh; off = i; }
    else if (i < 2 * NX4)           { src = ecg; dst = ecgh; off = i - NX4; }
    else {
        int wi = i - 2 * NX4;
        int w = wi / NW4;           // 0..3
        off = wi - w * NW4;
        src = (w == 0) ? Wq : (w == 1) ? Wk : (w == 2) ? Wv : Wo;
        dst = wh + (size_t)w * CC * CC;
    }
    float4 v = ((const float4*)src)[off];
    *(uint2*)&dst[(size_t)off * 4] = f4_to_h2x2(v);
}

// ---------------------------------------------------------------------------
// Merged Q/K/V projection, 128(l) x 128(c) tile (2 heads per CTA).
// Properly phased cp.async pipeline: wait at loop TOP on the group issued in
// the PREVIOUS iteration; one barrier per chunk. z = which*BB + b.
// ---------------------------------------------------------------------------
__global__ __launch_bounds__(256, 2) void qkv_proj(const __half* __restrict__ ppgh,
                                                   const __half* __restrict__ ecgh,
                                                   const __half* __restrict__ wh,
                                                   const float* __restrict__ bq,
                                                   const float* __restrict__ bk,
                                                   const float* __restrict__ bv,
                                                   __half* __restrict__ oq,
                                                   __half* __restrict__ ok,
                                                   __half* __restrict__ ov) {
    extern __shared__ char smraw[];
    __half* As = (__half*)smraw;           // [2][64][136]  (k, l)
    __half* Ws = As + 2 * 64 * 136;        // [2][128][72]  (c, k)
    float*  Es = (float*)smraw;            // epilogue reuse: [128][136] f32

    const int zz = blockIdx.z;
    const int which = zz >> 2;             // 0=q 1=k 2=v
    const int b = zz & 3;
    const __half* Xh = (which == 0) ? ppgh : ecgh;
    const __half* Wh = wh + (size_t)which * CC * CC;
    const float* bias = (which == 0) ? bq : (which == 1) ? bk : bv;
    __half* out = (which == 0) ? oq : (which == 1) ? ok : ov;

    const int l0 = blockIdx.x * 128;
    const int c0 = blockIdx.y * 128;
    const int tid = threadIdx.x;
    const int wid = tid >> 5;
    const int wm = wid & 3, wn = wid >> 2;

    const __half* Xb = Xh + (size_t)b * CC * LL;

    const int akr = tid >> 4, al8 = (tid & 15) * 8;
    const int wc  = tid >> 3, wk8 = (tid & 7) * 8;

    wmma::fragment<wmma::accumulator, 16, 16, 16, float> acc[2][4];
    #pragma unroll
    for (int i = 0; i < 2; i++)
        #pragma unroll
        for (int j = 0; j < 4; j++) wmma::fill_fragment(acc[i][j], 0.0f);

    // prologue: chunk 0 -> buf 0
    #pragma unroll
    for (int it = 0; it < 4; it++) {
        int kr = it * 16 + akr;
        cp_async16(smem_u32(&As[kr * 136 + al8]), &Xb[(size_t)kr * LL + l0 + al8]);
    }
    #pragma unroll
    for (int it = 0; it < 4; it++) {
        int c = it * 32 + wc;
        cp_async16(smem_u32(&Ws[c * 72 + wk8]), &Wh[(size_t)(c0 + c) * CC + wk8]);
    }
    cp_commit();

    for (int t = 0; t < 8; t++) {
        cp_wait0();            // group issued one iteration ago
        __syncthreads();       // buffer t visible; all done with t-1

        // prefetch t+1 into the buffer last read at t-1 (safe past barrier)
        if (t < 7) {
            const int nbuf = (t + 1) & 1;
            __half* An = As + nbuf * 64 * 136;
            __half* Wn = Ws + nbuf * 128 * 72;
            int k0 = (t + 1) * 64;
            #pragma unroll
            for (int it = 0; it < 4; it++) {
                int kr = it * 16 + akr;
                cp_async16(smem_u32(&An[kr * 136 + al8]),
                           &Xb[(size_t)(k0 + kr) * LL + l0 + al8]);
            }
            #pragma unroll
            for (int it = 0; it < 4; it++) {
                int c = it * 32 + wc;
                cp_async16(smem_u32(&Wn[c * 72 + wk8]),
                           &Wh[(size_t)(c0 + c) * CC + k0 + wk8]);
            }
            cp_commit();
        }

        const int buf = t & 1;
        __half* Ab = As + buf * 64 * 136;
        __half* Wb = Ws + buf * 128 * 72;

        #pragma unroll
        for (int ks = 0; ks < 4; ks++) {
            wmma::fragment<wmma::matrix_a, 16, 16, 16, __half, wmma::col_major> af[2];
            #pragma unroll
            for (int mt = 0; mt < 2; mt++)
                wmma::load_matrix_sync(af[mt], Ab + (ks * 16) * 136 + wm * 32 + mt * 16, 136);
            #pragma unroll
            for (int nt = 0; nt < 4; nt++) {
                wmma::fragment<wmma::matrix_b, 16, 16, 16, __half, wmma::col_major> bf;
                wmma::load_matrix_sync(bf, Wb + (wn * 64 + nt * 16) * 72 + ks * 16, 72);
                wmma::mma_sync(acc[0][nt], af[0], bf, acc[0][nt]);
                wmma::mma_sync(acc[1][nt], af[1], bf, acc[1][nt]);
            }
        }
    }
    __syncthreads();   // all compute done before Es aliases the staging smem

    // epilogue: Es[l][c] f32, ld 136
    #pragma unroll
    for (int mt = 0; mt < 2; mt++)
        #pragma unroll
        for (int nt = 0; nt < 4; nt++)
            wmma::store_matrix_sync(&Es[(wm * 32 + mt * 16) * 136 + wn * 64 + nt * 16],
                                    acc[mt][nt], 136, wmma::mem_row_major);
    __syncthreads();

    const int r = tid >> 1, hf = tid & 1;
    const int h = (c0 >> 6) + hf;
    __half* dst = out + ((size_t)((b * HH + h) * LL) + l0 + r) * DD;
    const float* es = &Es[r * 136 + hf * 64];
    const float* bs = &bias[c0 + hf * 64];
    #pragma unroll
    for (int j = 0; j < 64; j += 4) {
        float4 e = *(const float4*)&es[j];
        float4 bv4 = *(const float4*)&bs[j];
        *(uint2*)&dst[j] = f4_to_h2x2(make_float4(e.x + bv4.x, e.y + bv4.y,
                                                  e.z + bv4.z, e.w + bv4.w));
    }
}

// ---------------------------------------------------------------------------
// Fused attention v6 — register-resident P + MUFU exp, properly phased
// cp.async pipeline (wait at loop top, prefetch after barrier, one barrier
// per KV tile, copy overlaps full tile compute).
// ---------------------------------------------------------------------------
__global__ __launch_bounds__(256, 2)
void attn_ptx(const __half* __restrict__ q, const __half* __restrict__ k,
              const __half* __restrict__ v, __half* __restrict__ ctx) {
    extern __shared__ char smraw[];
    __half* Qh = (__half*)smraw;                 // [128][72]
    __half* Ks = Qh + 128 * 72;                  // [2][64][72]
    __half* Vs = Ks + 2 * 64 * 72;               // [2][64][72]

    const int bh  = blockIdx.y;
    const int q0  = blockIdx.x * 128;
    const int tid = threadIdx.x;
    const int wid = tid >> 5;
    const int rw  = wid * 16;
    const int lane = tid & 31;
    const int lrow = lane >> 2;
    const int lcol = lane & 3;

    const __half* qb = q + (size_t)bh * LL * DD;
    const __half* kb = k + (size_t)bh * LL * DD;
    const __half* vb = v + (size_t)bh * LL * DD;

    const int sr = tid >> 3;
    const int sd = (tid & 7) * 8;

    // prologue: Q + KV tile 0 in one group
    #pragma unroll
    for (int it = 0; it < 4; it++) {
        int r = it * 32 + sr;
        cp_async16(smem_u32(&Qh[r * 72 + sd]), &qb[(size_t)(q0 + r) * DD + sd]);
    }
    #pragma unroll
    for (int it = 0; it < 2; it++) {
        int r = it * 32 + sr;
        cp_async16(smem_u32(&Ks[r * 72 + sd]), &kb[(size_t)r * DD + sd]);
        cp_async16(smem_u32(&Vs[r * 72 + sd]), &vb[(size_t)r * DD + sd]);
    }
    cp_commit();
    cp_wait0();
    __syncthreads();

    unsigned qa[4][4];
    #pragma unroll
    for (int kg = 0; kg < 4; kg++) {
        unsigned addr = smem_u32(&Qh[(rw + (lane & 15)) * 72 + kg * 16 + (lane >> 4) * 8]);
        ldm_x4(qa[kg][0], qa[kg][1], qa[kg][2], qa[kg][3], addr);
    }

    float o[8][4];
    #pragma unroll
    for (int i = 0; i < 8; i++)
        #pragma unroll
        for (int j = 0; j < 4; j++) o[i][j] = 0.0f;
    float rs_lo = 0.0f, rs_hi = 0.0f;

    const int NT = LL / 64;
    for (int t = 0; t < NT; t++) {
        if (t > 0) {
            cp_wait0();        // group for tile t (issued during tile t-1)
            __syncthreads();   // buffer visible; all done reading buf t-1
        }
        // prefetch t+1 into the buffer last read at t-1 (safe past barrier)
        if (t + 1 < NT) {
            const int nxt = (t + 1) & 1;
            __half* Kn = Ks + nxt * 64 * 72;
            __half* Vn = Vs + nxt * 64 * 72;
            size_t base = (size_t)(t + 1) * 64 * DD;
            #pragma unroll
            for (int it = 0; it < 2; it++) {
                int r = it * 32 + sr;
                cp_async16(smem_u32(&Kn[r * 72 + sd]), &kb[base + (size_t)r * DD + sd]);
                cp_async16(smem_u32(&Vn[r * 72 + sd]), &vb[base + (size_t)r * DD + sd]);
            }
            cp_commit();
        }

        const int cur = t & 1;
        __half* Kc = Ks + cur * 64 * 72;
        __half* Vc = Vs + cur * 64 * 72;

        unsigned s[8][2];
        #pragma unroll
        for (int nb = 0; nb < 8; nb++) { s[nb][0] = 0u; s[nb][1] = 0u; }
        #pragma unroll
        for (int kg = 0; kg < 4; kg++) {
            #pragma unroll
            for (int nb2 = 0; nb2 < 4; nb2++) {
                unsigned r0, r1, r2, r3;
                unsigned addr = smem_u32(&Kc[(nb2 * 16 + (lane & 15)) * 72 +
                                             kg * 16 + (lane >> 4) * 8]);
                ldm_x4(r0, r1, r2, r3, addr);     // NON-trans: B[k][n]=K[key=n][d=k]
                mma16816_h(s[nb2 * 2][0], s[nb2 * 2][1],
                           qa[kg][0], qa[kg][1], qa[kg][2], qa[kg][3], r0, r2);
                mma16816_h(s[nb2 * 2 + 1][0], s[nb2 * 2 + 1][1],
                           qa[kg][0], qa[kg][1], qa[kg][2], qa[kg][3], r1, r3);
            }
        }

        #pragma unroll
        for (int nb = 0; nb < 8; nb++) {
            float2 f0 = __half22float2(*(__half2*)&s[nb][0]);
            float2 f1 = __half22float2(*(__half2*)&s[nb][1]);
            f0.x = ex2_fast(f0.x * EXP8_SCALE);
            f0.y = ex2_fast(f0.y * EXP8_SCALE);
            f1.x = ex2_fast(f1.x * EXP8_SCALE);
            f1.y = ex2_fast(f1.y * EXP8_SCALE);
            rs_lo += f0.x + f0.y;
            rs_hi += f1.x + f1.y;
            __half2 h0 = __floats2half2_rn(f0.x, f0.y);
            __half2 h1 = __floats2half2_rn(f1.x, f1.y);
            s[nb][0] = *(unsigned*)&h0;
            s[nb][1] = *(unsigned*)&h1;
        }

        #pragma unroll
        for (int kg2 = 0; kg2 < 4; kg2++) {
            unsigned a0 = s[kg2 * 2][0], a1 = s[kg2 * 2][1];
            unsigned a2 = s[kg2 * 2 + 1][0], a3 = s[kg2 * 2 + 1][1];
            #pragma unroll
            for (int db2 = 0; db2 < 4; db2++) {
                unsigned r0, r1, r2, r3;
                unsigned addr = smem_u32(&Vc[(kg2 * 16 + (lane & 15)) * 72 +
                                             db2 * 16 + (lane >> 4) * 8]);
                ldm_x4_t(r0, r1, r2, r3, addr);   // trans: B[k][n]=V[key=k][d=n]
                mma16816_f(o[db2 * 2][0], o[db2 * 2][1], o[db2 * 2][2], o[db2 * 2][3],
                           a0, a1, a2, a3, r0, r1);
                mma16816_f(o[db2 * 2 + 1][0], o[db2 * 2 + 1][1],
                           o[db2 * 2 + 1][2], o[db2 * 2 + 1][3],
                           a0, a1, a2, a3, r2, r3);
            }
        }
    }

    rs_lo += __shfl_xor_sync(0xffffffffu, rs_lo, 1);
    rs_lo += __shfl_xor_sync(0xffffffffu, rs_lo, 2);
    rs_hi += __shfl_xor_sync(0xffffffffu, rs_hi, 1);
    rs_hi += __shfl_xor_sync(0xffffffffu, rs_hi, 2);
    float inv_lo = 1.0f / rs_lo;
    float inv_hi = 1.0f / rs_hi;

    const int b = bh >> 3, h = bh & 7;
    const int row_lo = q0 + rw + lrow;
    __half* dst_lo = ctx + ((size_t)(b * LL + row_lo)) * CC + h * DD + 2 * lcol;
    __half* dst_hi = dst_lo + (size_t)8 * CC;
    #pragma unroll
    for (int db = 0; db < 8; db++) {
        __half2 lo = __floats2half2_rn(o[db][0] * inv_lo, o[db][1] * inv_lo);
        __half2 hi = __floats2half2_rn(o[db][2] * inv_hi, o[db][3] * inv_hi);
        *(__half2*)&dst_lo[db * 8] = lo;
        *(__half2*)&dst_hi[db * 8] = hi;
    }
}

// ---------------------------------------------------------------------------
// Output GEMM + residual, 128(c) x 128(l) tile, properly phased pipeline.
// ---------------------------------------------------------------------------
__global__ __launch_bounds__(256, 2) void outproj_h(const __half* __restrict__ ctxh,
                                                    const __half* __restrict__ Woh,
                                                    const float* __restrict__ bo,
                                                    const float* __restrict__ ppg,
                                                    float* __restrict__ out) {
    extern __shared__ char smraw[];
    __half* As = (__half*)smraw;           // [2][128][72] (c, k)
    __half* Cs = As + 2 * 128 * 72;        // [2][128][72] (l, k)
    float*  Es = (float*)smraw;            // epilogue reuse [128][136] f32

    const int b  = blockIdx.z;
    const int l0 = blockIdx.x * 128;
    const int c0 = blockIdx.y * 128;
    const int tid = threadIdx.x;
    const int wid = tid >> 5;
    const int wm = wid & 3, wn = wid >> 2;

    const __half* ctxb = ctxh + (size_t)b * LL * CC;

    const int ac = tid >> 3, ak8 = (tid & 7) * 8;

    wmma::fragment<wmma::accumulator, 16, 16, 16, float> acc[2][4];
    #pragma unroll
    for (int i = 0; i < 2; i++)
        #pragma unroll
        for (int j = 0; j < 4; j++) wmma::fill_fragment(acc[i][j], 0.0f);

    // prologue: chunk 0
    #pragma unroll
    for (int it = 0; it < 4; it++) {
        int c = it * 32 + ac;
        cp_async16(smem_u32(&As[c * 72 + ak8]), &Woh[(size_t)(c0 + c) * CC + ak8]);
    }
    #pragma unroll
    for (int it = 0; it < 4; it++) {
        int l = it * 32 + ac;
        cp_async16(smem_u32(&Cs[l * 72 + ak8]), &ctxb[(size_t)(l0 + l) * CC + ak8]);
    }
    cp_commit();

    for (int t = 0; t < 8; t++) {
        cp_wait0();
        __syncthreads();

        if (t < 7) {
            const int nbuf = (t + 1) & 1;
            __half* An = As + nbuf * 128 * 72;
            __half* Cn = Cs + nbuf * 128 * 72;
            int k0 = (t + 1) * 64;
            #pragma unroll
            for (int it = 0; it < 4; it++) {
                int c = it * 32 + ac;
                cp_async16(smem_u32(&An[c * 72 + ak8]),
                           &Woh[(size_t)(c0 + c) * CC + k0 + ak8]);
            }
            #pragma unroll
            for (int it = 0; it < 4; it++) {
                int l = it * 32 + ac;
                cp_async16(smem_u32(&Cn[l * 72 + ak8]),
                           &ctxb[(size_t)(l0 + l) * CC + k0 + ak8]);
            }
            cp_commit();
        }

        const int buf = t & 1;
        __half* Ab = As + buf * 128 * 72;
        __half* Cb = Cs + buf * 128 * 72;

        #pragma unroll
        for (int ks = 0; ks < 4; ks++) {
            wmma::fragment<wmma::matrix_a, 16, 16, 16, __half, wmma::row_major> af[2];
            #pragma unroll
            for (int mt = 0; mt < 2; mt++)
                wmma::load_matrix_sync(af[mt], Ab + (wm * 32 + mt * 16) * 72 + ks * 16, 72);
            #pragma unroll
            for (int nt = 0; nt < 4; nt++) {
                wmma::fragment<wmma::matrix_b, 16, 16, 16, __half, wmma::col_major> bf;
                wmma::load_matrix_sync(bf, Cb + (wn * 64 + nt * 16) * 72 + ks * 16, 72);
                wmma::mma_sync(acc[0][nt], af[0], bf, acc[0][nt]);
                wmma::mma_sync(acc[1][nt], af[1], bf, acc[1][nt]);
            }
        }
    }
    __syncthreads();

    // epilogue: Es[c][l] f32, ld 136
    #pragma unroll
    for (int mt = 0; mt < 2; mt++)
        #pragma unroll
        for (int nt = 0; nt < 4; nt++)
            wmma::store_matrix_sync(&Es[(wm * 32 + mt * 16) * 136 + wn * 64 + nt * 16],
                                    acc[mt][nt], 136, wmma::mem_row_major);
    __syncthreads();

    const int r = tid >> 1, hf = tid & 1;
    const int c = c0 + r;
    float bias = bo[c];
    size_t base = (size_t)b * CC * LL + (size_t)c * LL + l0 + hf * 64;
    const float* es = &Es[r * 136 + hf * 64];
    #pragma unroll
    for (int j = 0; j < 64; j += 4) {
        float4 e = *(const float4*)&es[j];
        float4 pv = *(const float4*)&ppg[base + j];
        *(float4*)&out[base + j] = make_float4(e.x + bias + pv.x, e.y + bias + pv.y,
                                               e.z + bias + pv.z, e.w + bias + pv.w);
    }
}

// ---------------------------------------------------------------------------
extern "C" void kernel_launch(void* const* d_in, const int* in_sizes, int n_in,
                              void* d_out, int out_size) {
    const float* ppg = (const float*)d_in[0];
    const float* ecg = (const float*)d_in[1];
    const float* Wq  = (const float*)d_in[2];
    const float* bq  = (const float*)d_in[3];
    const float* Wk  = (const float*)d_in[4];
    const float* bk  = (const float*)d_in[5];
    const float* Wv  = (const float*)d_in[6];
    const float* bv  = (const float*)d_in[7];
    const float* Wo  = (const float*)d_in[8];
    const float* bo  = (const float*)d_in[9];
    float* out = (float*)d_out;

    __half *pq, *pk, *pv, *pctx, *pppgh, *pecgh, *pwh;
    cudaGetSymbolAddress((void**)&pq,    g_q);
    cudaGetSymbolAddress((void**)&pk,    g_k);
    cudaGetSymbolAddress((void**)&pv,    g_v);
    cudaGetSymbolAddress((void**)&pctx,  g_ctx);
    cudaGetSymbolAddress((void**)&pppgh, g_ppgh);
    cudaGetSymbolAddress((void**)&pecgh, g_ecgh);
    cudaGetSymbolAddress((void**)&pwh,   g_wh);

    const int total4 = 2 * NX4 + 4 * NW4;
    cvt_all<<<(total4 + 255) / 256, 256>>>(ppg, ecg, Wq, Wk, Wv, Wo,
                                           pppgh, pecgh, pwh);

    // merged projections: 128x128 tiles, z = which*BB + b
    int smemP = 2 * 64 * 136 * 2 + 2 * 128 * 72 * 2;   // 71680
    cudaFuncSetAttribute(qkv_proj, cudaFuncAttributeMaxDynamicSharedMemorySize, smemP);
    dim3 gridP(LL / 128, CC / 128, 3 * BB);
    qkv_proj<<<gridP, 256, smemP>>>(pppgh, pecgh, pwh, bq, bk, bv, pq, pk, pv);

    // attention: Qh 18432 + Ks 18432 + Vs 18432 = 55296 B
    int smemA = (128 * 72 + 2 * 64 * 72 + 2 * 64 * 72) * 2;
    cudaFuncSetAttribute(attn_ptx, cudaFuncAttributeMaxDynamicSharedMemorySize, smemA);
    dim3 gridA(LL / 128, BB * HH);
    attn_ptx<<<gridA, 256, smemA>>>(pq, pk, pv, pctx);

    // output projection: 128x128 tiles
    int smemO = 2 * 128 * 72 * 2 + 2 * 128 * 72 * 2;   // 73728
    cudaFuncSetAttribute(outproj_h, cudaFuncAttributeMaxDynamicSharedMemorySize, smemO);
    dim3 gridO(LL / 128, CC / 128, BB);
    outproj_h<<<gridO, 256, smemO>>>(pctx, pwh + 3 * CC * CC, bo, ppg, out);
}

// round 13
// speedup vs baseline: 1.0312x; 1.0312x over previous
#include <cuda_runtime.h>
#include <cuda_fp16.h>
#include <mma.h>
#include <cstdint>

using namespace nvcuda;

#define BB   4
#define HH   8
#define LL   2048
#define CC   512
#define DD   64

// fp16 scratch (allocation-free rule: __device__ globals)
__device__ __half g_q[BB*HH*LL*DD];
__device__ __half g_k[BB*HH*LL*DD];
__device__ __half g_v[BB*HH*LL*DD];
__device__ __half g_ctx[(size_t)BB*LL*CC];
__device__ __half g_ppgh[(size_t)BB*CC*LL];
__device__ __half g_ecgh[(size_t)BB*CC*LL];
__device__ __half g_wh[4*CC*CC];     // Wq | Wk | Wv | Wo

__device__ __forceinline__ uint2 f4_to_h2x2(float4 v) {
    __half2 a = __floats2half2_rn(v.x, v.y);
    __half2 b = __floats2half2_rn(v.z, v.w);
    uint2 r;
    r.x = *(unsigned int*)&a;
    r.y = *(unsigned int*)&b;
    return r;
}

// exp(s*0.125) via MUFU: ex2.approx(s * 0.125*log2(e)). rel err ~2^-22.
__device__ __forceinline__ float ex2_fast(float x) {
    float y;
    asm("ex2.approx.f32 %0, %1;" : "=f"(y) : "f"(x));
    return y;
}
#define EXP8_SCALE 0.18033688011f

// ---- PTX wrappers -----------------------------------------------------------
__device__ __forceinline__ unsigned smem_u32(const void* p) {
    return (unsigned)__cvta_generic_to_shared(p);
}
__device__ __forceinline__ void ldm_x4(unsigned& r0, unsigned& r1, unsigned& r2,
                                       unsigned& r3, unsigned addr) {
    asm volatile("ldmatrix.sync.aligned.m8n8.x4.shared.b16 {%0,%1,%2,%3}, [%4];"
                 : "=r"(r0), "=r"(r1), "=r"(r2), "=r"(r3) : "r"(addr));
}
__device__ __forceinline__ void ldm_x4_t(unsigned& r0, unsigned& r1, unsigned& r2,
                                         unsigned& r3, unsigned addr) {
    asm volatile("ldmatrix.sync.aligned.m8n8.x4.trans.shared.b16 {%0,%1,%2,%3}, [%4];"
                 : "=r"(r0), "=r"(r1), "=r"(r2), "=r"(r3) : "r"(addr));
}
__device__ __forceinline__ void mma16816_h(unsigned& c0, unsigned& c1,
                                           unsigned a0, unsigned a1, unsigned a2,
                                           unsigned a3, unsigned b0, unsigned b1) {
    asm volatile("mma.sync.aligned.m16n8k16.row.col.f16.f16.f16.f16 "
                 "{%0,%1}, {%2,%3,%4,%5}, {%6,%7}, {%0,%1};"
                 : "+r"(c0), "+r"(c1)
                 : "r"(a0), "r"(a1), "r"(a2), "r"(a3), "r"(b0), "r"(b1));
}
__device__ __forceinline__ void mma16816_f(float& d0, float& d1, float& d2, float& d3,
                                           unsigned a0, unsigned a1, unsigned a2,
                                           unsigned a3, unsigned b0, unsigned b1) {
    asm volatile("mma.sync.aligned.m16n8k16.row.col.f32.f16.f16.f32 "
                 "{%0,%1,%2,%3}, {%4,%5,%6,%7}, {%8,%9}, {%0,%1,%2,%3};"
                 : "+f"(d0), "+f"(d1), "+f"(d2), "+f"(d3)
                 : "r"(a0), "r"(a1), "r"(a2), "r"(a3), "r"(b0), "r"(b1));
}
__device__ __forceinline__ void cp_async16(unsigned dst, const void* src) {
    asm volatile("cp.async.ca.shared.global [%0], [%1], 16;"
                 :: "r"(dst), "l"(src));
}
__device__ __forceinline__ void cp_commit() {
    asm volatile("cp.async.commit_group;");
}
__device__ __forceinline__ void cp_wait0() {
    asm volatile("cp.async.wait_group 0;");
}

// ---------------------------------------------------------------------------
// One fused fp32->fp16 conversion for all 6 tensors.
// ---------------------------------------------------------------------------
#define NX4 (BB*CC*LL/4)
#define NW4 (CC*CC/4)
__global__ void cvt_all(const float* __restrict__ ppg, const float* __restrict__ ecg,
                        const float* __restrict__ Wq, const float* __restrict__ Wk,
                        const float* __restrict__ Wv, const float* __restrict__ Wo,
                        __half* __restrict__ ppgh, __half* __restrict__ ecgh,
                        __half* __restrict__ wh) {
    int i = blockIdx.x * blockDim.x + threadIdx.x;
    const float* src;
    __half* dst;
    int off;
    if (i < NX4)                    { src = ppg; dst = ppgh; off = i; }
    else if (i < 2 * NX4)           { src = ecg; dst = ecgh; off = i - NX4; }
    else {
        int wi = i - 2 * NX4;
        int w = wi / NW4;           // 0..3
        off = wi - w * NW4;
        src = (w == 0) ? Wq : (w == 1) ? Wk : (w == 2) ? Wv : Wo;
        dst = wh + (size_t)w * CC * CC;
    }
    float4 v = ((const float4*)src)[off];
    *(uint2*)&dst[(size_t)off * 4] = f4_to_h2x2(v);
}

// ---------------------------------------------------------------------------
// Merged Q/K/V projection, 128(l) x 128(c) tile, fp16 ACCUMULATORS.
// R11 pipeline structure (wait at loop bottom). z = which*BB + b.
// ---------------------------------------------------------------------------
__global__ __launch_bounds__(256, 2) void qkv_proj(const __half* __restrict__ ppgh,
                                                   const __half* __restrict__ ecgh,
                                                   const __half* __restrict__ wh,
                                                   const float* __restrict__ bq,
                                                   const float* __restrict__ bk,
                                                   const float* __restrict__ bv,
                                                   __half* __restrict__ oq,
                                                   __half* __restrict__ ok,
                                                   __half* __restrict__ ov) {
    extern __shared__ char smraw[];
    __half* As = (__half*)smraw;           // [2][64][136]  (k, l)
    __half* Ws = As + 2 * 64 * 136;        // [2][128][72]  (c, k)
    __half* Esh = (__half*)smraw;          // epilogue reuse: [128][136] fp16

    const int zz = blockIdx.z;
    const int which = zz >> 2;             // 0=q 1=k 2=v
    const int b = zz & 3;
    const __half* Xh = (which == 0) ? ppgh : ecgh;
    const __half* Wh = wh + (size_t)which * CC * CC;
    const float* bias = (which == 0) ? bq : (which == 1) ? bk : bv;
    __half* out = (which == 0) ? oq : (which == 1) ? ok : ov;

    const int l0 = blockIdx.x * 128;
    const int c0 = blockIdx.y * 128;
    const int tid = threadIdx.x;
    const int wid = tid >> 5;
    const int wm = wid & 3, wn = wid >> 2;

    const __half* Xb = Xh + (size_t)b * CC * LL;

    const int akr = tid >> 4, al8 = (tid & 15) * 8;
    const int wc  = tid >> 3, wk8 = (tid & 7) * 8;

    wmma::fragment<wmma::accumulator, 16, 16, 16, __half> acc[2][4];
    #pragma unroll
    for (int i = 0; i < 2; i++)
        #pragma unroll
        for (int j = 0; j < 4; j++) wmma::fill_fragment(acc[i][j], __float2half(0.0f));

    // prologue: chunk 0 -> buf 0
    #pragma unroll
    for (int it = 0; it < 4; it++) {
        int kr = it * 16 + akr;
        cp_async16(smem_u32(&As[kr * 136 + al8]), &Xb[(size_t)kr * LL + l0 + al8]);
    }
    #pragma unroll
    for (int it = 0; it < 4; it++) {
        int c = it * 32 + wc;
        cp_async16(smem_u32(&Ws[c * 72 + wk8]), &Wh[(size_t)(c0 + c) * CC + wk8]);
    }
    cp_commit();
    cp_wait0();
    __syncthreads();

    for (int t = 0; t < 8; t++) {
        const int buf = t & 1;
        __half* Ab = As + buf * 64 * 136;
        __half* Wb = Ws + buf * 128 * 72;

        if (t < 7) {
            const int nbuf = buf ^ 1;
            __half* An = As + nbuf * 64 * 136;
            __half* Wn = Ws + nbuf * 128 * 72;
            int k0 = (t + 1) * 64;
            #pragma unroll
            for (int it = 0; it < 4; it++) {
                int kr = it * 16 + akr;
                cp_async16(smem_u32(&An[kr * 136 + al8]),
                           &Xb[(size_t)(k0 + kr) * LL + l0 + al8]);
            }
            #pragma unroll
            for (int it = 0; it < 4; it++) {
                int c = it * 32 + wc;
                cp_async16(smem_u32(&Wn[c * 72 + wk8]),
                           &Wh[(size_t)(c0 + c) * CC + k0 + wk8]);
            }
            cp_commit();
        }

        #pragma unroll
        for (int ks = 0; ks < 4; ks++) {
            wmma::fragment<wmma::matrix_a, 16, 16, 16, __half, wmma::col_major> af[2];
            #pragma unroll
            for (int mt = 0; mt < 2; mt++)
                wmma::load_matrix_sync(af[mt], Ab + (ks * 16) * 136 + wm * 32 + mt * 16, 136);
            #pragma unroll
            for (int nt = 0; nt < 4; nt++) {
                wmma::fragment<wmma::matrix_b, 16, 16, 16, __half, wmma::col_major> bf;
                wmma::load_matrix_sync(bf, Wb + (wn * 64 + nt * 16) * 72 + ks * 16, 72);
                wmma::mma_sync(acc[0][nt], af[0], bf, acc[0][nt]);
                wmma::mma_sync(acc[1][nt], af[1], bf, acc[1][nt]);
            }
        }

        cp_wait0();
        __syncthreads();
    }

    // epilogue: Esh[l][c] fp16, ld 136
    #pragma unroll
    for (int mt = 0; mt < 2; mt++)
        #pragma unroll
        for (int nt = 0; nt < 4; nt++)
            wmma::store_matrix_sync(&Esh[(wm * 32 + mt * 16) * 136 + wn * 64 + nt * 16],
                                    acc[mt][nt], 136, wmma::mem_row_major);
    __syncthreads();

    const int r = tid >> 1, hf = tid & 1;
    const int h = (c0 >> 6) + hf;
    __half* dst = out + ((size_t)((b * HH + h) * LL) + l0 + r) * DD;
    const __half* es = &Esh[r * 136 + hf * 64];
    const float* bs = &bias[c0 + hf * 64];
    #pragma unroll
    for (int j = 0; j < 64; j += 4) {
        __half2 e01 = *(const __half2*)&es[j];
        __half2 e23 = *(const __half2*)&es[j + 2];
        float2 f01 = __half22float2(e01);
        float2 f23 = __half22float2(e23);
        float4 bv4 = *(const float4*)&bs[j];
        *(uint2*)&dst[j] = f4_to_h2x2(make_float4(f01.x + bv4.x, f01.y + bv4.y,
                                                  f23.x + bv4.z, f23.y + bv4.w));
    }
}

// ---------------------------------------------------------------------------
// Fused attention (exact R11/R10 structure — register-resident P, MUFU exp,
// cp.async double-buffer with wait at loop bottom).
// ---------------------------------------------------------------------------
__global__ __launch_bounds__(256, 2)
void attn_ptx(const __half* __restrict__ q, const __half* __restrict__ k,
              const __half* __restrict__ v, __half* __restrict__ ctx) {
    extern __shared__ char smraw[];
    __half* Qh = (__half*)smraw;                 // [128][72]
    __half* Ks = Qh + 128 * 72;                  // [2][64][72]
    __half* Vs = Ks + 2 * 64 * 72;               // [2][64][72]

    const int bh  = blockIdx.y;
    const int q0  = blockIdx.x * 128;
    const int tid = threadIdx.x;
    const int wid = tid >> 5;
    const int rw  = wid * 16;
    const int lane = tid & 31;
    const int lrow = lane >> 2;
    const int lcol = lane & 3;

    const __half* qb = q + (size_t)bh * LL * DD;
    const __half* kb = k + (size_t)bh * LL * DD;
    const __half* vb = v + (size_t)bh * LL * DD;

    const int sr = tid >> 3;
    const int sd = (tid & 7) * 8;

    #pragma unroll
    for (int it = 0; it < 4; it++) {
        int r = it * 32 + sr;
        cp_async16(smem_u32(&Qh[r * 72 + sd]), &qb[(size_t)(q0 + r) * DD + sd]);
    }
    #pragma unroll
    for (int it = 0; it < 2; it++) {
        int r = it * 32 + sr;
        cp_async16(smem_u32(&Ks[r * 72 + sd]), &kb[(size_t)r * DD + sd]);
        cp_async16(smem_u32(&Vs[r * 72 + sd]), &vb[(size_t)r * DD + sd]);
    }
    cp_commit();
    cp_wait0();
    __syncthreads();

    unsigned qa[4][4];
    #pragma unroll
    for (int kg = 0; kg < 4; kg++) {
        unsigned addr = smem_u32(&Qh[(rw + (lane & 15)) * 72 + kg * 16 + (lane >> 4) * 8]);
        ldm_x4(qa[kg][0], qa[kg][1], qa[kg][2], qa[kg][3], addr);
    }

    float o[8][4];
    #pragma unroll
    for (int i = 0; i < 8; i++)
        #pragma unroll
        for (int j = 0; j < 4; j++) o[i][j] = 0.0f;
    float rs_lo = 0.0f, rs_hi = 0.0f;

    const int NT = LL / 64;
    for (int t = 0; t < NT; t++) {
        const int cur = t & 1;
        __half* Kc = Ks + cur * 64 * 72;
        __half* Vc = Vs + cur * 64 * 72;

        if (t + 1 < NT) {
            const int nxt = (t + 1) & 1;
            __half* Kn = Ks + nxt * 64 * 72;
            __half* Vn = Vs + nxt * 64 * 72;
            size_t base = (size_t)(t + 1) * 64 * DD;
            #pragma unroll
            for (int it = 0; it < 2; it++) {
                int r = it * 32 + sr;
                cp_async16(smem_u32(&Kn[r * 72 + sd]), &kb[base + (size_t)r * DD + sd]);
                cp_async16(smem_u32(&Vn[r * 72 + sd]), &vb[base + (size_t)r * DD + sd]);
            }
            cp_commit();
        }

        unsigned s[8][2];
        #pragma unroll
        for (int nb = 0; nb < 8; nb++) { s[nb][0] = 0u; s[nb][1] = 0u; }
        #pragma unroll
        for (int kg = 0; kg < 4; kg++) {
            #pragma unroll
            for (int nb2 = 0; nb2 < 4; nb2++) {
                unsigned r0, r1, r2, r3;
                unsigned addr = smem_u32(&Kc[(nb2 * 16 + (lane & 15)) * 72 +
                                             kg * 16 + (lane >> 4) * 8]);
                ldm_x4(r0, r1, r2, r3, addr);     // NON-trans: B[k][n]=K[key=n][d=k]
                mma16816_h(s[nb2 * 2][0], s[nb2 * 2][1],
                           qa[kg][0], qa[kg][1], qa[kg][2], qa[kg][3], r0, r2);
                mma16816_h(s[nb2 * 2 + 1][0], s[nb2 * 2 + 1][1],
                           qa[kg][0], qa[kg][1], qa[kg][2], qa[kg][3], r1, r3);
            }
        }

        #pragma unroll
        for (int nb = 0; nb < 8; nb++) {
            float2 f0 = __half22float2(*(__half2*)&s[nb][0]);
            float2 f1 = __half22float2(*(__half2*)&s[nb][1]);
            f0.x = ex2_fast(f0.x * EXP8_SCALE);
            f0.y = ex2_fast(f0.y * EXP8_SCALE);
            f1.x = ex2_fast(f1.x * EXP8_SCALE);
            f1.y = ex2_fast(f1.y * EXP8_SCALE);
            rs_lo += f0.x + f0.y;
            rs_hi += f1.x + f1.y;
            __half2 h0 = __floats2half2_rn(f0.x, f0.y);
            __half2 h1 = __floats2half2_rn(f1.x, f1.y);
            s[nb][0] = *(unsigned*)&h0;
            s[nb][1] = *(unsigned*)&h1;
        }

        #pragma unroll
        for (int kg2 = 0; kg2 < 4; kg2++) {
            unsigned a0 = s[kg2 * 2][0], a1 = s[kg2 * 2][1];
            unsigned a2 = s[kg2 * 2 + 1][0], a3 = s[kg2 * 2 + 1][1];
            #pragma unroll
            for (int db2 = 0; db2 < 4; db2++) {
                unsigned r0, r1, r2, r3;
                unsigned addr = smem_u32(&Vc[(kg2 * 16 + (lane & 15)) * 72 +
                                             db2 * 16 + (lane >> 4) * 8]);
                ldm_x4_t(r0, r1, r2, r3, addr);   // trans: B[k][n]=V[key=k][d=n]
                mma16816_f(o[db2 * 2][0], o[db2 * 2][1], o[db2 * 2][2], o[db2 * 2][3],
                           a0, a1, a2, a3, r0, r1);
                mma16816_f(o[db2 * 2 + 1][0], o[db2 * 2 + 1][1],
                           o[db2 * 2 + 1][2], o[db2 * 2 + 1][3],
                           a0, a1, a2, a3, r2, r3);
            }
        }

        cp_wait0();
        __syncthreads();
    }

    rs_lo += __shfl_xor_sync(0xffffffffu, rs_lo, 1);
    rs_lo += __shfl_xor_sync(0xffffffffu, rs_lo, 2);
    rs_hi += __shfl_xor_sync(0xffffffffu, rs_hi, 1);
    rs_hi += __shfl_xor_sync(0xffffffffu, rs_hi, 2);
    float inv_lo = 1.0f / rs_lo;
    float inv_hi = 1.0f / rs_hi;

    const int b = bh >> 3, h = bh & 7;
    const int row_lo = q0 + rw + lrow;
    __half* dst_lo = ctx + ((size_t)(b * LL + row_lo)) * CC + h * DD + 2 * lcol;
    __half* dst_hi = dst_lo + (size_t)8 * CC;
    #pragma unroll
    for (int db = 0; db < 8; db++) {
        __half2 lo = __floats2half2_rn(o[db][0] * inv_lo, o[db][1] * inv_lo);
        __half2 hi = __floats2half2_rn(o[db][2] * inv_hi, o[db][3] * inv_hi);
        *(__half2*)&dst_lo[db * 8] = lo;
        *(__half2*)&dst_hi[db * 8] = hi;
    }
}

// ---------------------------------------------------------------------------
// Output GEMM + residual, 128(c) x 128(l) tile, fp16 ACCUMULATORS.
// R11 pipeline structure (wait at loop bottom). Residual + bias in fp32.
// ---------------------------------------------------------------------------
__global__ __launch_bounds__(256, 2) void outproj_h(const __half* __restrict__ ctxh,
                                                    const __half* __restrict__ Woh,
                                                    const float* __restrict__ bo,
                                                    const float* __restrict__ ppg,
                                                    float* __restrict__ out) {
    extern __shared__ char smraw[];
    __half* As = (__half*)smraw;           // [2][128][72] (c, k)
    __half* Cs = As + 2 * 128 * 72;        // [2][128][72] (l, k)
    __half* Esh = (__half*)smraw;          // epilogue reuse [128][136] fp16

    const int b  = blockIdx.z;
    const int l0 = blockIdx.x * 128;
    const int c0 = blockIdx.y * 128;
    const int tid = threadIdx.x;
    const int wid = tid >> 5;
    const int wm = wid & 3, wn = wid >> 2;

    const __half* ctxb = ctxh + (size_t)b * LL * CC;

    const int ac = tid >> 3, ak8 = (tid & 7) * 8;

    wmma::fragment<wmma::accumulator, 16, 16, 16, __half> acc[2][4];
    #pragma unroll
    for (int i = 0; i < 2; i++)
        #pragma unroll
        for (int j = 0; j < 4; j++) wmma::fill_fragment(acc[i][j], __float2half(0.0f));

    // prologue: chunk 0
    #pragma unroll
    for (int it = 0; it < 4; it++) {
        int c = it * 32 + ac;
        cp_async16(smem_u32(&As[c * 72 + ak8]), &Woh[(size_t)(c0 + c) * CC + ak8]);
    }
    #pragma unroll
    for (int it = 0; it < 4; it++) {
        int l = it * 32 + ac;
        cp_async16(smem_u32(&Cs[l * 72 + ak8]), &ctxb[(size_t)(l0 + l) * CC + ak8]);
    }
    cp_commit();
    cp_wait0();
    __syncthreads();

    for (int t = 0; t < 8; t++) {
        const int buf = t & 1;
        __half* Ab = As + buf * 128 * 72;
        __half* Cb = Cs + buf * 128 * 72;

        if (t < 7) {
            const int nbuf = buf ^ 1;
            __half* An = As + nbuf * 128 * 72;
            __half* Cn = Cs + nbuf * 128 * 72;
            int k0 = (t + 1) * 64;
            #pragma unroll
            for (int it = 0; it < 4; it++) {
                int c = it * 32 + ac;
                cp_async16(smem_u32(&An[c * 72 + ak8]),
                           &Woh[(size_t)(c0 + c) * CC + k0 + ak8]);
            }
            #pragma unroll
            for (int it = 0; it < 4; it++) {
                int l = it * 32 + ac;
                cp_async16(smem_u32(&Cn[l * 72 + ak8]),
                           &ctxb[(size_t)(l0 + l) * CC + k0 + ak8]);
            }
            cp_commit();
        }

        #pragma unroll
        for (int ks = 0; ks < 4; ks++) {
            wmma::fragment<wmma::matrix_a, 16, 16, 16, __half, wmma::row_major> af[2];
            #pragma unroll
            for (int mt = 0; mt < 2; mt++)
                wmma::load_matrix_sync(af[mt], Ab + (wm * 32 + mt * 16) * 72 + ks * 16, 72);
            #pragma unroll
            for (int nt = 0; nt < 4; nt++) {
                wmma::fragment<wmma::matrix_b, 16, 16, 16, __half, wmma::col_major> bf;
                wmma::load_matrix_sync(bf, Cb + (wn * 64 + nt * 16) * 72 + ks * 16, 72);
                wmma::mma_sync(acc[0][nt], af[0], bf, acc[0][nt]);
                wmma::mma_sync(acc[1][nt], af[1], bf, acc[1][nt]);
            }
        }

        cp_wait0();
        __syncthreads();
    }

    // epilogue: Esh[c][l] fp16, ld 136
    #pragma unroll
    for (int mt = 0; mt < 2; mt++)
        #pragma unroll
        for (int nt = 0; nt < 4; nt++)
            wmma::store_matrix_sync(&Esh[(wm * 32 + mt * 16) * 136 + wn * 64 + nt * 16],
                                    acc[mt][nt], 136, wmma::mem_row_major);
    __syncthreads();

    const int r = tid >> 1, hf = tid & 1;
    const int c = c0 + r;
    float bias = bo[c];
    size_t base = (size_t)b * CC * LL + (size_t)c * LL + l0 + hf * 64;
    const __half* es = &Esh[r * 136 + hf * 64];
    #pragma unroll
    for (int j = 0; j < 64; j += 4) {
        __half2 e01 = *(const __half2*)&es[j];
        __half2 e23 = *(const __half2*)&es[j + 2];
        float2 f01 = __half22float2(e01);
        float2 f23 = __half22float2(e23);
        float4 pv = *(const float4*)&ppg[base + j];
        *(float4*)&out[base + j] = make_float4(f01.x + bias + pv.x, f01.y + bias + pv.y,
                                               f23.x + bias + pv.z, f23.y + bias + pv.w);
    }
}

// ---------------------------------------------------------------------------
extern "C" void kernel_launch(void* const* d_in, const int* in_sizes, int n_in,
                              void* d_out, int out_size) {
    const float* ppg = (const float*)d_in[0];
    const float* ecg = (const float*)d_in[1];
    const float* Wq  = (const float*)d_in[2];
    const float* bq  = (const float*)d_in[3];
    const float* Wk  = (const float*)d_in[4];
    const float* bk  = (const float*)d_in[5];
    const float* Wv  = (const float*)d_in[6];
    const float* bv  = (const float*)d_in[7];
    const float* Wo  = (const float*)d_in[8];
    const float* bo  = (const float*)d_in[9];
    float* out = (float*)d_out;

    __half *pq, *pk, *pv, *pctx, *pppgh, *pecgh, *pwh;
    cudaGetSymbolAddress((void**)&pq,    g_q);
    cudaGetSymbolAddress((void**)&pk,    g_k);
    cudaGetSymbolAddress((void**)&pv,    g_v);
    cudaGetSymbolAddress((void**)&pctx,  g_ctx);
    cudaGetSymbolAddress((void**)&pppgh, g_ppgh);
    cudaGetSymbolAddress((void**)&pecgh, g_ecgh);
    cudaGetSymbolAddress((void**)&pwh,   g_wh);

    const int total4 = 2 * NX4 + 4 * NW4;
    cvt_all<<<(total4 + 255) / 256, 256>>>(ppg, ecg, Wq, Wk, Wv, Wo,
                                           pppgh, pecgh, pwh);

    // merged projections: 128x128 tiles, z = which*BB + b
    int smemP = 2 * 64 * 136 * 2 + 2 * 128 * 72 * 2;   // 71680
    cudaFuncSetAttribute(qkv_proj, cudaFuncAttributeMaxDynamicSharedMemorySize, smemP);
    dim3 gridP(LL / 128, CC / 128, 3 * BB);
    qkv_proj<<<gridP, 256, smemP>>>(pppgh, pecgh, pwh, bq, bk, bv, pq, pk, pv);

    // attention: Qh 18432 + Ks 18432 + Vs 18432 = 55296 B
    int smemA = (128 * 72 + 2 * 64 * 72 + 2 * 64 * 72) * 2;
    cudaFuncSetAttribute(attn_ptx, cudaFuncAttributeMaxDynamicSharedMemorySize, smemA);
    dim3 gridA(LL / 128, BB * HH);
    attn_ptx<<<gridA, 256, smemA>>>(pq, pk, pv, pctx);

    // output projection: 128x128 tiles
    int smemO = 2 * 128 * 72 * 2 + 2 * 128 * 72 * 2;   // 73728
    cudaFuncSetAttribute(outproj_h, cudaFuncAttributeMaxDynamicSharedMemorySize, smemO);
    dim3 gridO(LL / 128, CC / 128, BB);
    outproj_h<<<gridO, 256, smemO>>>(pctx, pwh + 3 * CC * CC, bo, ppg, out);
}

// round 14
// speedup vs baseline: 1.0438x; 1.0123x over previous
#include <cuda_runtime.h>
#include <cuda_fp16.h>
#include <mma.h>
#include <cstdint>

using namespace nvcuda;

#define BB   4
#define HH   8
#define LL   2048
#define CC   512
#define DD   64

// fp16 scratch (allocation-free rule: __device__ globals)
__device__ __half g_q[BB*HH*LL*DD];
__device__ __half g_k[BB*HH*LL*DD];
__device__ __half g_v[BB*HH*LL*DD];
__device__ __half g_ctx[(size_t)BB*LL*CC];
__device__ __half g_ppgh[(size_t)BB*CC*LL];
__device__ __half g_ecgh[(size_t)BB*CC*LL];
__device__ __half g_wh[4*CC*CC];     // Wq | Wk | Wv | Wo

__device__ __forceinline__ uint2 f4_to_h2x2(float4 v) {
    __half2 a = __floats2half2_rn(v.x, v.y);
    __half2 b = __floats2half2_rn(v.z, v.w);
    uint2 r;
    r.x = *(unsigned int*)&a;
    r.y = *(unsigned int*)&b;
    return r;
}

// packed f16x2: out = 2^(in * scale2)   (exp(s/8) with scale = 0.125*log2e)
__device__ __forceinline__ unsigned exp8_h2(unsigned s, unsigned scale2) {
    unsigned t, y;
    asm("mul.rn.f16x2 %0, %1, %2;" : "=r"(t) : "r"(s), "r"(scale2));
    asm("ex2.approx.f16x2 %0, %1;" : "=r"(y) : "r"(t));
    return y;
}

// ---- PTX wrappers -----------------------------------------------------------
__device__ __forceinline__ unsigned smem_u32(const void* p) {
    return (unsigned)__cvta_generic_to_shared(p);
}
__device__ __forceinline__ void ldm_x4(unsigned& r0, unsigned& r1, unsigned& r2,
                                       unsigned& r3, unsigned addr) {
    asm volatile("ldmatrix.sync.aligned.m8n8.x4.shared.b16 {%0,%1,%2,%3}, [%4];"
                 : "=r"(r0), "=r"(r1), "=r"(r2), "=r"(r3) : "r"(addr));
}
__device__ __forceinline__ void ldm_x4_t(unsigned& r0, unsigned& r1, unsigned& r2,
                                         unsigned& r3, unsigned addr) {
    asm volatile("ldmatrix.sync.aligned.m8n8.x4.trans.shared.b16 {%0,%1,%2,%3}, [%4];"
                 : "=r"(r0), "=r"(r1), "=r"(r2), "=r"(r3) : "r"(addr));
}
__device__ __forceinline__ void mma16816_h(unsigned& c0, unsigned& c1,
                                           unsigned a0, unsigned a1, unsigned a2,
                                           unsigned a3, unsigned b0, unsigned b1) {
    asm volatile("mma.sync.aligned.m16n8k16.row.col.f16.f16.f16.f16 "
                 "{%0,%1}, {%2,%3,%4,%5}, {%6,%7}, {%0,%1};"
                 : "+r"(c0), "+r"(c1)
                 : "r"(a0), "r"(a1), "r"(a2), "r"(a3), "r"(b0), "r"(b1));
}
__device__ __forceinline__ void mma16816_f(float& d0, float& d1, float& d2, float& d3,
                                           unsigned a0, unsigned a1, unsigned a2,
                                           unsigned a3, unsigned b0, unsigned b1) {
    asm volatile("mma.sync.aligned.m16n8k16.row.col.f32.f16.f16.f32 "
                 "{%0,%1,%2,%3}, {%4,%5,%6,%7}, {%8,%9}, {%0,%1,%2,%3};"
                 : "+f"(d0), "+f"(d1), "+f"(d2), "+f"(d3)
                 : "r"(a0), "r"(a1), "r"(a2), "r"(a3), "r"(b0), "r"(b1));
}
__device__ __forceinline__ void cp_async16(unsigned dst, const void* src) {
    asm volatile("cp.async.ca.shared.global [%0], [%1], 16;"
                 :: "r"(dst), "l"(src));
}
__device__ __forceinline__ void cp_commit() {
    asm volatile("cp.async.commit_group;");
}
__device__ __forceinline__ void cp_wait0() {
    asm volatile("cp.async.wait_group 0;");
}

// ---------------------------------------------------------------------------
// One fused fp32->fp16 conversion for all 6 tensors.
// ---------------------------------------------------------------------------
#define NX4 (BB*CC*LL/4)
#define NW4 (CC*CC/4)
__global__ void cvt_all(const float* __restrict__ ppg, const float* __restrict__ ecg,
                        const float* __restrict__ Wq, const float* __restrict__ Wk,
                        const float* __restrict__ Wv, const float* __restrict__ Wo,
                        __half* __restrict__ ppgh, __half* __restrict__ ecgh,
                        __half* __restrict__ wh) {
    int i = blockIdx.x * blockDim.x + threadIdx.x;
    const float* src;
    __half* dst;
    int off;
    if (i < NX4)                    { src = ppg; dst = ppgh; off = i; }
    else if (i < 2 * NX4)           { src = ecg; dst = ecgh; off = i - NX4; }
    else {
        int wi = i - 2 * NX4;
        int w = wi / NW4;           // 0..3
        off = wi - w * NW4;
        src = (w == 0) ? Wq : (w == 1) ? Wk : (w == 2) ? Wv : Wo;
        dst = wh + (size_t)w * CC * CC;
    }
    float4 v = ((const float4*)src)[off];
    *(uint2*)&dst[(size_t)off * 4] = f4_to_h2x2(v);
}

// ---------------------------------------------------------------------------
// Merged Q/K/V projection, 128(l) x 128(c) tile, fp16 accumulators (R13).
// ---------------------------------------------------------------------------
__global__ __launch_bounds__(256, 2) void qkv_proj(const __half* __restrict__ ppgh,
                                                   const __half* __restrict__ ecgh,
                                                   const __half* __restrict__ wh,
                                                   const float* __restrict__ bq,
                                                   const float* __restrict__ bk,
                                                   const float* __restrict__ bv,
                                                   __half* __restrict__ oq,
                                                   __half* __restrict__ ok,
                                                   __half* __restrict__ ov) {
    extern __shared__ char smraw[];
    __half* As = (__half*)smraw;           // [2][64][136]  (k, l)
    __half* Ws = As + 2 * 64 * 136;        // [2][128][72]  (c, k)
    __half* Esh = (__half*)smraw;          // epilogue reuse: [128][136] fp16

    const int zz = blockIdx.z;
    const int which = zz >> 2;             // 0=q 1=k 2=v
    const int b = zz & 3;
    const __half* Xh = (which == 0) ? ppgh : ecgh;
    const __half* Wh = wh + (size_t)which * CC * CC;
    const float* bias = (which == 0) ? bq : (which == 1) ? bk : bv;
    __half* out = (which == 0) ? oq : (which == 1) ? ok : ov;

    const int l0 = blockIdx.x * 128;
    const int c0 = blockIdx.y * 128;
    const int tid = threadIdx.x;
    const int wid = tid >> 5;
    const int wm = wid & 3, wn = wid >> 2;

    const __half* Xb = Xh + (size_t)b * CC * LL;

    const int akr = tid >> 4, al8 = (tid & 15) * 8;
    const int wc  = tid >> 3, wk8 = (tid & 7) * 8;

    wmma::fragment<wmma::accumulator, 16, 16, 16, __half> acc[2][4];
    #pragma unroll
    for (int i = 0; i < 2; i++)
        #pragma unroll
        for (int j = 0; j < 4; j++) wmma::fill_fragment(acc[i][j], __float2half(0.0f));

    #pragma unroll
    for (int it = 0; it < 4; it++) {
        int kr = it * 16 + akr;
        cp_async16(smem_u32(&As[kr * 136 + al8]), &Xb[(size_t)kr * LL + l0 + al8]);
    }
    #pragma unroll
    for (int it = 0; it < 4; it++) {
        int c = it * 32 + wc;
        cp_async16(smem_u32(&Ws[c * 72 + wk8]), &Wh[(size_t)(c0 + c) * CC + wk8]);
    }
    cp_commit();
    cp_wait0();
    __syncthreads();

    for (int t = 0; t < 8; t++) {
        const int buf = t & 1;
        __half* Ab = As + buf * 64 * 136;
        __half* Wb = Ws + buf * 128 * 72;

        if (t < 7) {
            const int nbuf = buf ^ 1;
            __half* An = As + nbuf * 64 * 136;
            __half* Wn = Ws + nbuf * 128 * 72;
            int k0 = (t + 1) * 64;
            #pragma unroll
            for (int it = 0; it < 4; it++) {
                int kr = it * 16 + akr;
                cp_async16(smem_u32(&An[kr * 136 + al8]),
                           &Xb[(size_t)(k0 + kr) * LL + l0 + al8]);
            }
            #pragma unroll
            for (int it = 0; it < 4; it++) {
                int c = it * 32 + wc;
                cp_async16(smem_u32(&Wn[c * 72 + wk8]),
                           &Wh[(size_t)(c0 + c) * CC + k0 + wk8]);
            }
            cp_commit();
        }

        #pragma unroll
        for (int ks = 0; ks < 4; ks++) {
            wmma::fragment<wmma::matrix_a, 16, 16, 16, __half, wmma::col_major> af[2];
            #pragma unroll
            for (int mt = 0; mt < 2; mt++)
                wmma::load_matrix_sync(af[mt], Ab + (ks * 16) * 136 + wm * 32 + mt * 16, 136);
            #pragma unroll
            for (int nt = 0; nt < 4; nt++) {
                wmma::fragment<wmma::matrix_b, 16, 16, 16, __half, wmma::col_major> bf;
                wmma::load_matrix_sync(bf, Wb + (wn * 64 + nt * 16) * 72 + ks * 16, 72);
                wmma::mma_sync(acc[0][nt], af[0], bf, acc[0][nt]);
                wmma::mma_sync(acc[1][nt], af[1], bf, acc[1][nt]);
            }
        }

        cp_wait0();
        __syncthreads();
    }

    #pragma unroll
    for (int mt = 0; mt < 2; mt++)
        #pragma unroll
        for (int nt = 0; nt < 4; nt++)
            wmma::store_matrix_sync(&Esh[(wm * 32 + mt * 16) * 136 + wn * 64 + nt * 16],
                                    acc[mt][nt], 136, wmma::mem_row_major);
    __syncthreads();

    const int r = tid >> 1, hf = tid & 1;
    const int h = (c0 >> 6) + hf;
    __half* dst = out + ((size_t)((b * HH + h) * LL) + l0 + r) * DD;
    const __half* es = &Esh[r * 136 + hf * 64];
    const float* bs = &bias[c0 + hf * 64];
    #pragma unroll
    for (int j = 0; j < 64; j += 4) {
        __half2 e01 = *(const __half2*)&es[j];
        __half2 e23 = *(const __half2*)&es[j + 2];
        float2 f01 = __half22float2(e01);
        float2 f23 = __half22float2(e23);
        float4 bv4 = *(const float4*)&bs[j];
        *(uint2*)&dst[j] = f4_to_h2x2(make_float4(f01.x + bv4.x, f01.y + bv4.y,
                                                  f23.x + bv4.z, f23.y + bv4.w));
    }
}

// ---------------------------------------------------------------------------
// Fused attention v7 — f16x2 MUFU exp in-place + rowsum via ones-column mma.
//   V smem stride 88: cols 64-79 hold {1,0,...} (written once, cp.async only
//   writes cols 0-63). One extra ldsm+mma per kg2 yields row sums on the
//   tensor pipe; softmax issue-block shrinks ~3x.
// ---------------------------------------------------------------------------
__global__ __launch_bounds__(256, 2)
void attn_ptx(const __half* __restrict__ q, const __half* __restrict__ k,
              const __half* __restrict__ v, __half* __restrict__ ctx) {
    extern __shared__ char smraw[];
    __half* Qh = (__half*)smraw;                 // [128][72]   18432 B
    __half* Ks = Qh + 128 * 72;                  // [2][64][72] 18432 B
    __half* Vs = Ks + 2 * 64 * 72;               // [2][64][88] 22528 B

    const int bh  = blockIdx.y;
    const int q0  = blockIdx.x * 128;
    const int tid = threadIdx.x;
    const int wid = tid >> 5;
    const int rw  = wid * 16;
    const int lane = tid & 31;
    const int lrow = lane >> 2;
    const int lcol = lane & 3;

    const __half* qb = q + (size_t)bh * LL * DD;
    const __half* kb = k + (size_t)bh * LL * DD;
    const __half* vb = v + (size_t)bh * LL * DD;

    const int sr = tid >> 3;
    const int sd = (tid & 7) * 8;

    const unsigned scale2 = 0x31C531C5u;   // half2(0.18034, 0.18034) = 0.125*log2e

    // ones/zero pad for V cols 64..79 (both buffers, written once)
    if (tid < 128) {
        int buf = tid >> 6, r = tid & 63;
        *(uint4*)&Vs[(buf * 64 + r) * 88 + 64] = make_uint4(0x00003C00u, 0u, 0u, 0u);
        *(uint4*)&Vs[(buf * 64 + r) * 88 + 72] = make_uint4(0u, 0u, 0u, 0u);
    }

    #pragma unroll
    for (int it = 0; it < 4; it++) {
        int r = it * 32 + sr;
        cp_async16(smem_u32(&Qh[r * 72 + sd]), &qb[(size_t)(q0 + r) * DD + sd]);
    }
    #pragma unroll
    for (int it = 0; it < 2; it++) {
        int r = it * 32 + sr;
        cp_async16(smem_u32(&Ks[r * 72 + sd]), &kb[(size_t)r * DD + sd]);
        cp_async16(smem_u32(&Vs[r * 88 + sd]), &vb[(size_t)r * DD + sd]);
    }
    cp_commit();
    cp_wait0();
    __syncthreads();

    unsigned qa[4][4];
    #pragma unroll
    for (int kg = 0; kg < 4; kg++) {
        unsigned addr = smem_u32(&Qh[(rw + (lane & 15)) * 72 + kg * 16 + (lane >> 4) * 8]);
        ldm_x4(qa[kg][0], qa[kg][1], qa[kg][2], qa[kg][3], addr);
    }

    float o[8][4];
    #pragma unroll
    for (int i = 0; i < 8; i++)
        #pragma unroll
        for (int j = 0; j < 4; j++) o[i][j] = 0.0f;
    float o5[4] = {0.f, 0.f, 0.f, 0.f};   // ones-column accumulator (rowsums)

    const int NT = LL / 64;
    for (int t = 0; t < NT; t++) {
        const int cur = t & 1;
        __half* Kc = Ks + cur * 64 * 72;
        __half* Vc = Vs + cur * 64 * 88;

        if (t + 1 < NT) {
            const int nxt = (t + 1) & 1;
            __half* Kn = Ks + nxt * 64 * 72;
            __half* Vn = Vs + nxt * 64 * 88;
            size_t base = (size_t)(t + 1) * 64 * DD;
            #pragma unroll
            for (int it = 0; it < 2; it++) {
                int r = it * 32 + sr;
                cp_async16(smem_u32(&Kn[r * 72 + sd]), &kb[base + (size_t)r * DD + sd]);
                cp_async16(smem_u32(&Vn[r * 88 + sd]), &vb[base + (size_t)r * DD + sd]);
            }
            cp_commit();
        }

        // ---- S = Q @ K^T (fp16 accum) ----
        unsigned s[8][2];
        #pragma unroll
        for (int nb = 0; nb < 8; nb++) { s[nb][0] = 0u; s[nb][1] = 0u; }
        #pragma unroll
        for (int kg = 0; kg < 4; kg++) {
            #pragma unroll
            for (int nb2 = 0; nb2 < 4; nb2++) {
                unsigned r0, r1, r2, r3;
                unsigned addr = smem_u32(&Kc[(nb2 * 16 + (lane & 15)) * 72 +
                                             kg * 16 + (lane >> 4) * 8]);
                ldm_x4(r0, r1, r2, r3, addr);     // NON-trans: B[k][n]=K[key=n][d=k]
                mma16816_h(s[nb2 * 2][0], s[nb2 * 2][1],
                           qa[kg][0], qa[kg][1], qa[kg][2], qa[kg][3], r0, r2);
                mma16816_h(s[nb2 * 2 + 1][0], s[nb2 * 2 + 1][1],
                           qa[kg][0], qa[kg][1], qa[kg][2], qa[kg][3], r1, r3);
            }
        }

        // ---- P = exp(S/8), packed f16x2 MUFU, in place ----
        #pragma unroll
        for (int nb = 0; nb < 8; nb++) {
            s[nb][0] = exp8_h2(s[nb][0], scale2);
            s[nb][1] = exp8_h2(s[nb][1], scale2);
        }

        // ---- O += P @ V ; rowsum via ones columns (col 64) ----
        #pragma unroll
        for (int kg2 = 0; kg2 < 4; kg2++) {
            unsigned a0 = s[kg2 * 2][0], a1 = s[kg2 * 2][1];
            unsigned a2 = s[kg2 * 2 + 1][0], a3 = s[kg2 * 2 + 1][1];
            #pragma unroll
            for (int db2 = 0; db2 < 4; db2++) {
                unsigned r0, r1, r2, r3;
                unsigned addr = smem_u32(&Vc[(kg2 * 16 + (lane & 15)) * 88 +
                                             db2 * 16 + (lane >> 4) * 8]);
                ldm_x4_t(r0, r1, r2, r3, addr);   // trans: B[k][n]=V[key=k][d=n]
                mma16816_f(o[db2 * 2][0], o[db2 * 2][1], o[db2 * 2][2], o[db2 * 2][3],
                           a0, a1, a2, a3, r0, r1);
                mma16816_f(o[db2 * 2 + 1][0], o[db2 * 2 + 1][1],
                           o[db2 * 2 + 1][2], o[db2 * 2 + 1][3],
                           a0, a1, a2, a3, r2, r3);
            }
            {   // ones block: cols 64-79, keep only first 8 cols
                unsigned r0, r1, r2, r3;
                unsigned addr = smem_u32(&Vc[(kg2 * 16 + (lane & 15)) * 88 +
                                             64 + (lane >> 4) * 8]);
                ldm_x4_t(r0, r1, r2, r3, addr);
                mma16816_f(o5[0], o5[1], o5[2], o5[3], a0, a1, a2, a3, r0, r1);
            }
        }

        cp_wait0();
        __syncthreads();
    }

    // rowsums live in ones-column (col 64 = block col 0, owned by lcol==0)
    float rs_lo = __shfl_sync(0xffffffffu, o5[0], lane & 28);
    float rs_hi = __shfl_sync(0xffffffffu, o5[2], lane & 28);
    float inv_lo = 1.0f / rs_lo;
    float inv_hi = 1.0f / rs_hi;

    const int b = bh >> 3, h = bh & 7;
    const int row_lo = q0 + rw + lrow;
    __half* dst_lo = ctx + ((size_t)(b * LL + row_lo)) * CC + h * DD + 2 * lcol;
    __half* dst_hi = dst_lo + (size_t)8 * CC;
    #pragma unroll
    for (int db = 0; db < 8; db++) {
        __half2 lo = __floats2half2_rn(o[db][0] * inv_lo, o[db][1] * inv_lo);
        __half2 hi = __floats2half2_rn(o[db][2] * inv_hi, o[db][3] * inv_hi);
        *(__half2*)&dst_lo[db * 8] = lo;
        *(__half2*)&dst_hi[db * 8] = hi;
    }
}

// ---------------------------------------------------------------------------
// Output GEMM + residual, 128(c) x 128(l) tile, fp16 accumulators (R13).
// ---------------------------------------------------------------------------
__global__ __launch_bounds__(256, 2) void outproj_h(const __half* __restrict__ ctxh,
                                                    const __half* __restrict__ Woh,
                                                    const float* __restrict__ bo,
                                                    const float* __restrict__ ppg,
                                                    float* __restrict__ out) {
    extern __shared__ char smraw[];
    __half* As = (__half*)smraw;           // [2][128][72] (c, k)
    __half* Cs = As + 2 * 128 * 72;        // [2][128][72] (l, k)
    __half* Esh = (__half*)smraw;          // epilogue reuse [128][136] fp16

    const int b  = blockIdx.z;
    const int l0 = blockIdx.x * 128;
    const int c0 = blockIdx.y * 128;
    const int tid = threadIdx.x;
    const int wid = tid >> 5;
    const int wm = wid & 3, wn = wid >> 2;

    const __half* ctxb = ctxh + (size_t)b * LL * CC;

    const int ac = tid >> 3, ak8 = (tid & 7) * 8;

    wmma::fragment<wmma::accumulator, 16, 16, 16, __half> acc[2][4];
    #pragma unroll
    for (int i = 0; i < 2; i++)
        #pragma unroll
        for (int j = 0; j < 4; j++) wmma::fill_fragment(acc[i][j], __float2half(0.0f));

    #pragma unroll
    for (int it = 0; it < 4; it++) {
        int c = it * 32 + ac;
        cp_async16(smem_u32(&As[c * 72 + ak8]), &Woh[(size_t)(c0 + c) * CC + ak8]);
    }
    #pragma unroll
    for (int it = 0; it < 4; it++) {
        int l = it * 32 + ac;
        cp_async16(smem_u32(&Cs[l * 72 + ak8]), &ctxb[(size_t)(l0 + l) * CC + ak8]);
    }
    cp_commit();
    cp_wait0();
    __syncthreads();

    for (int t = 0; t < 8; t++) {
        const int buf = t & 1;
        __half* Ab = As + buf * 128 * 72;
        __half* Cb = Cs + buf * 128 * 72;

        if (t < 7) {
            const int nbuf = buf ^ 1;
            __half* An = As + nbuf * 128 * 72;
            __half* Cn = Cs + nbuf * 128 * 72;
            int k0 = (t + 1) * 64;
            #pragma unroll
            for (int it = 0; it < 4; it++) {
                int c = it * 32 + ac;
                cp_async16(smem_u32(&An[c * 72 + ak8]),
                           &Woh[(size_t)(c0 + c) * CC + k0 + ak8]);
            }
            #pragma unroll
            for (int it = 0; it < 4; it++) {
                int l = it * 32 + ac;
                cp_async16(smem_u32(&Cn[l * 72 + ak8]),
                           &ctxb[(size_t)(l0 + l) * CC + k0 + ak8]);
            }
            cp_commit();
        }

        #pragma unroll
        for (int ks = 0; ks < 4; ks++) {
            wmma::fragment<wmma::matrix_a, 16, 16, 16, __half, wmma::row_major> af[2];
            #pragma unroll
            for (int mt = 0; mt < 2; mt++)
                wmma::load_matrix_sync(af[mt], Ab + (wm * 32 + mt * 16) * 72 + ks * 16, 72);
            #pragma unroll
            for (int nt = 0; nt < 4; nt++) {
                wmma::fragment<wmma::matrix_b, 16, 16, 16, __half, wmma::col_major> bf;
                wmma::load_matrix_sync(bf, Cb + (wn * 64 + nt * 16) * 72 + ks * 16, 72);
                wmma::mma_sync(acc[0][nt], af[0], bf, acc[0][nt]);
                wmma::mma_sync(acc[1][nt], af[1], bf, acc[1][nt]);
            }
        }

        cp_wait0();
        __syncthreads();
    }

    #pragma unroll
    for (int mt = 0; mt < 2; mt++)
        #pragma unroll
        for (int nt = 0; nt < 4; nt++)
            wmma::store_matrix_sync(&Esh[(wm * 32 + mt * 16) * 136 + wn * 64 + nt * 16],
                                    acc[mt][nt], 136, wmma::mem_row_major);
    __syncthreads();

    const int r = tid >> 1, hf = tid & 1;
    const int c = c0 + r;
    float bias = bo[c];
    size_t base = (size_t)b * CC * LL + (size_t)c * LL + l0 + hf * 64;
    const __half* es = &Esh[r * 136 + hf * 64];
    #pragma unroll
    for (int j = 0; j < 64; j += 4) {
        __half2 e01 = *(const __half2*)&es[j];
        __half2 e23 = *(const __half2*)&es[j + 2];
        float2 f01 = __half22float2(e01);
        float2 f23 = __half22float2(e23);
        float4 pv = *(const float4*)&ppg[base + j];
        *(float4*)&out[base + j] = make_float4(f01.x + bias + pv.x, f01.y + bias + pv.y,
                                               f23.x + bias + pv.z, f23.y + bias + pv.w);
    }
}

// ---------------------------------------------------------------------------
extern "C" void kernel_launch(void* const* d_in, const int* in_sizes, int n_in,
                              void* d_out, int out_size) {
    const float* ppg = (const float*)d_in[0];
    const float* ecg = (const float*)d_in[1];
    const float* Wq  = (const float*)d_in[2];
    const float* bq  = (const float*)d_in[3];
    const float* Wk  = (const float*)d_in[4];
    const float* bk  = (const float*)d_in[5];
    const float* Wv  = (const float*)d_in[6];
    const float* bv  = (const float*)d_in[7];
    const float* Wo  = (const float*)d_in[8];
    const float* bo  = (const float*)d_in[9];
    float* out = (float*)d_out;

    __half *pq, *pk, *pv, *pctx, *pppgh, *pecgh, *pwh;
    cudaGetSymbolAddress((void**)&pq,    g_q);
    cudaGetSymbolAddress((void**)&pk,    g_k);
    cudaGetSymbolAddress((void**)&pv,    g_v);
    cudaGetSymbolAddress((void**)&pctx,  g_ctx);
    cudaGetSymbolAddress((void**)&pppgh, g_ppgh);
    cudaGetSymbolAddress((void**)&pecgh, g_ecgh);
    cudaGetSymbolAddress((void**)&pwh,   g_wh);

    const int total4 = 2 * NX4 + 4 * NW4;
    cvt_all<<<(total4 + 255) / 256, 256>>>(ppg, ecg, Wq, Wk, Wv, Wo,
                                           pppgh, pecgh, pwh);

    // merged projections: 128x128 tiles, z = which*BB + b
    int smemP = 2 * 64 * 136 * 2 + 2 * 128 * 72 * 2;   // 71680
    cudaFuncSetAttribute(qkv_proj, cudaFuncAttributeMaxDynamicSharedMemorySize, smemP);
    dim3 gridP(LL / 128, CC / 128, 3 * BB);
    qkv_proj<<<gridP, 256, smemP>>>(pppgh, pecgh, pwh, bq, bk, bv, pq, pk, pv);

    // attention: Qh 18432 + Ks 18432 + Vs 22528 = 59392 B
    int smemA = 128 * 72 * 2 + 2 * 64 * 72 * 2 + 2 * 64 * 88 * 2;
    cudaFuncSetAttribute(attn_ptx, cudaFuncAttributeMaxDynamicSharedMemorySize, smemA);
    dim3 gridA(LL / 128, BB * HH);
    attn_ptx<<<gridA, 256, smemA>>>(pq, pk, pv, pctx);

    // output projection: 128x128 tiles
    int smemO = 2 * 128 * 72 * 2 + 2 * 128 * 72 * 2;   // 73728
    cudaFuncSetAttribute(outproj_h, cudaFuncAttributeMaxDynamicSharedMemorySize, smemO);
    dim3 gridO(LL / 128, CC / 128, BB);
    outproj_h<<<gridO, 256, smemO>>>(pctx, pwh + 3 * CC * CC, bo, ppg, out);
}

// round 15
// speedup vs baseline: 1.0448x; 1.0010x over previous
#include <cuda_runtime.h>
#include <cuda_fp16.h>
#include <mma.h>
#include <cstdint>

using namespace nvcuda;

#define BB   4
#define HH   8
#define LL   2048
#define CC   512
#define DD   64

// fp16 scratch (allocation-free rule: __device__ globals)
__device__ __half g_q[BB*HH*LL*DD];
__device__ __half g_k[BB*HH*LL*DD];
__device__ __half g_v[BB*HH*LL*DD];
__device__ __half g_ctx[(size_t)BB*LL*CC];
__device__ __half g_ppgh[(size_t)BB*CC*LL];
__device__ __half g_ecgh[(size_t)BB*CC*LL];
__device__ __half g_wh[4*CC*CC];     // Wq | Wk | Wv | Wo

__device__ __forceinline__ uint2 f4_to_h2x2(float4 v) {
    __half2 a = __floats2half2_rn(v.x, v.y);
    __half2 b = __floats2half2_rn(v.z, v.w);
    uint2 r;
    r.x = *(unsigned int*)&a;
    r.y = *(unsigned int*)&b;
    return r;
}

// packed f16x2: out = 2^(in * scale2)   (exp(s/8) with scale = 0.125*log2e)
__device__ __forceinline__ unsigned exp8_h2(unsigned s, unsigned scale2) {
    unsigned t, y;
    asm("mul.rn.f16x2 %0, %1, %2;" : "=r"(t) : "r"(s), "r"(scale2));
    asm("ex2.approx.f16x2 %0, %1;" : "=r"(y) : "r"(t));
    return y;
}

// ---- PTX wrappers -----------------------------------------------------------
__device__ __forceinline__ unsigned smem_u32(const void* p) {
    return (unsigned)__cvta_generic_to_shared(p);
}
__device__ __forceinline__ void ldm_x4(unsigned& r0, unsigned& r1, unsigned& r2,
                                       unsigned& r3, unsigned addr) {
    asm volatile("ldmatrix.sync.aligned.m8n8.x4.shared.b16 {%0,%1,%2,%3}, [%4];"
                 : "=r"(r0), "=r"(r1), "=r"(r2), "=r"(r3) : "r"(addr));
}
__device__ __forceinline__ void ldm_x4_t(unsigned& r0, unsigned& r1, unsigned& r2,
                                         unsigned& r3, unsigned addr) {
    asm volatile("ldmatrix.sync.aligned.m8n8.x4.trans.shared.b16 {%0,%1,%2,%3}, [%4];"
                 : "=r"(r0), "=r"(r1), "=r"(r2), "=r"(r3) : "r"(addr));
}
__device__ __forceinline__ void mma16816_h(unsigned& c0, unsigned& c1,
                                           unsigned a0, unsigned a1, unsigned a2,
                                           unsigned a3, unsigned b0, unsigned b1) {
    asm volatile("mma.sync.aligned.m16n8k16.row.col.f16.f16.f16.f16 "
                 "{%0,%1}, {%2,%3,%4,%5}, {%6,%7}, {%0,%1};"
                 : "+r"(c0), "+r"(c1)
                 : "r"(a0), "r"(a1), "r"(a2), "r"(a3), "r"(b0), "r"(b1));
}
__device__ __forceinline__ void cp_async16(unsigned dst, const void* src) {
    asm volatile("cp.async.ca.shared.global [%0], [%1], 16;"
                 :: "r"(dst), "l"(src));
}
__device__ __forceinline__ void cp_commit() {
    asm volatile("cp.async.commit_group;");
}
__device__ __forceinline__ void cp_wait0() {
    asm volatile("cp.async.wait_group 0;");
}

// ---------------------------------------------------------------------------
// One fused fp32->fp16 conversion for all 6 tensors.
// ---------------------------------------------------------------------------
#define NX4 (BB*CC*LL/4)
#define NW4 (CC*CC/4)
__global__ void cvt_all(const float* __restrict__ ppg, const float* __restrict__ ecg,
                        const float* __restrict__ Wq, const float* __restrict__ Wk,
                        const float* __restrict__ Wv, const float* __restrict__ Wo,
                        __half* __restrict__ ppgh, __half* __restrict__ ecgh,
                        __half* __restrict__ wh) {
    int i = blockIdx.x * blockDim.x + threadIdx.x;
    const float* src;
    __half* dst;
    int off;
    if (i < NX4)                    { src = ppg; dst = ppgh; off = i; }
    else if (i < 2 * NX4)           { src = ecg; dst = ecgh; off = i - NX4; }
    else {
        int wi = i - 2 * NX4;
        int w = wi / NW4;           // 0..3
        off = wi - w * NW4;
        src = (w == 0) ? Wq : (w == 1) ? Wk : (w == 2) ? Wv : Wo;
        dst = wh + (size_t)w * CC * CC;
    }
    float4 v = ((const float4*)src)[off];
    *(uint2*)&dst[(size_t)off * 4] = f4_to_h2x2(v);
}

// ---------------------------------------------------------------------------
// Merged Q/K/V projection, 128(l) x 128(c) tile, fp16 accumulators (R14).
// ---------------------------------------------------------------------------
__global__ __launch_bounds__(256, 2) void qkv_proj(const __half* __restrict__ ppgh,
                                                   const __half* __restrict__ ecgh,
                                                   const __half* __restrict__ wh,
                                                   const float* __restrict__ bq,
                                                   const float* __restrict__ bk,
                                                   const float* __restrict__ bv,
                                                   __half* __restrict__ oq,
                                                   __half* __restrict__ ok,
                                                   __half* __restrict__ ov) {
    extern __shared__ char smraw[];
    __half* As = (__half*)smraw;           // [2][64][136]  (k, l)
    __half* Ws = As + 2 * 64 * 136;        // [2][128][72]  (c, k)
    __half* Esh = (__half*)smraw;          // epilogue reuse: [128][136] fp16

    const int zz = blockIdx.z;
    const int which = zz >> 2;             // 0=q 1=k 2=v
    const int b = zz & 3;
    const __half* Xh = (which == 0) ? ppgh : ecgh;
    const __half* Wh = wh + (size_t)which * CC * CC;
    const float* bias = (which == 0) ? bq : (which == 1) ? bk : bv;
    __half* out = (which == 0) ? oq : (which == 1) ? ok : ov;

    const int l0 = blockIdx.x * 128;
    const int c0 = blockIdx.y * 128;
    const int tid = threadIdx.x;
    const int wid = tid >> 5;
    const int wm = wid & 3, wn = wid >> 2;

    const __half* Xb = Xh + (size_t)b * CC * LL;

    const int akr = tid >> 4, al8 = (tid & 15) * 8;
    const int wc  = tid >> 3, wk8 = (tid & 7) * 8;

    wmma::fragment<wmma::accumulator, 16, 16, 16, __half> acc[2][4];
    #pragma unroll
    for (int i = 0; i < 2; i++)
        #pragma unroll
        for (int j = 0; j < 4; j++) wmma::fill_fragment(acc[i][j], __float2half(0.0f));

    #pragma unroll
    for (int it = 0; it < 4; it++) {
        int kr = it * 16 + akr;
        cp_async16(smem_u32(&As[kr * 136 + al8]), &Xb[(size_t)kr * LL + l0 + al8]);
    }
    #pragma unroll
    for (int it = 0; it < 4; it++) {
        int c = it * 32 + wc;
        cp_async16(smem_u32(&Ws[c * 72 + wk8]), &Wh[(size_t)(c0 + c) * CC + wk8]);
    }
    cp_commit();
    cp_wait0();
    __syncthreads();

    for (int t = 0; t < 8; t++) {
        const int buf = t & 1;
        __half* Ab = As + buf * 64 * 136;
        __half* Wb = Ws + buf * 128 * 72;

        if (t < 7) {
            const int nbuf = buf ^ 1;
            __half* An = As + nbuf * 64 * 136;
            __half* Wn = Ws + nbuf * 128 * 72;
            int k0 = (t + 1) * 64;
            #pragma unroll
            for (int it = 0; it < 4; it++) {
                int kr = it * 16 + akr;
                cp_async16(smem_u32(&An[kr * 136 + al8]),
                           &Xb[(size_t)(k0 + kr) * LL + l0 + al8]);
            }
            #pragma unroll
            for (int it = 0; it < 4; it++) {
                int c = it * 32 + wc;
                cp_async16(smem_u32(&Wn[c * 72 + wk8]),
                           &Wh[(size_t)(c0 + c) * CC + k0 + wk8]);
            }
            cp_commit();
        }

        #pragma unroll
        for (int ks = 0; ks < 4; ks++) {
            wmma::fragment<wmma::matrix_a, 16, 16, 16, __half, wmma::col_major> af[2];
            #pragma unroll
            for (int mt = 0; mt < 2; mt++)
                wmma::load_matrix_sync(af[mt], Ab + (ks * 16) * 136 + wm * 32 + mt * 16, 136);
            #pragma unroll
            for (int nt = 0; nt < 4; nt++) {
                wmma::fragment<wmma::matrix_b, 16, 16, 16, __half, wmma::col_major> bf;
                wmma::load_matrix_sync(bf, Wb + (wn * 64 + nt * 16) * 72 + ks * 16, 72);
                wmma::mma_sync(acc[0][nt], af[0], bf, acc[0][nt]);
                wmma::mma_sync(acc[1][nt], af[1], bf, acc[1][nt]);
            }
        }

        cp_wait0();
        __syncthreads();
    }

    #pragma unroll
    for (int mt = 0; mt < 2; mt++)
        #pragma unroll
        for (int nt = 0; nt < 4; nt++)
            wmma::store_matrix_sync(&Esh[(wm * 32 + mt * 16) * 136 + wn * 64 + nt * 16],
                                    acc[mt][nt], 136, wmma::mem_row_major);
    __syncthreads();

    const int r = tid >> 1, hf = tid & 1;
    const int h = (c0 >> 6) + hf;
    __half* dst = out + ((size_t)((b * HH + h) * LL) + l0 + r) * DD;
    const __half* es = &Esh[r * 136 + hf * 64];
    const float* bs = &bias[c0 + hf * 64];
    #pragma unroll
    for (int j = 0; j < 64; j += 4) {
        __half2 e01 = *(const __half2*)&es[j];
        __half2 e23 = *(const __half2*)&es[j + 2];
        float2 f01 = __half22float2(e01);
        float2 f23 = __half22float2(e23);
        float4 bv4 = *(const float4*)&bs[j];
        *(uint2*)&dst[j] = f4_to_h2x2(make_float4(f01.x + bv4.x, f01.y + bv4.y,
                                                  f23.x + bv4.z, f23.y + bv4.w));
    }
}

// ---------------------------------------------------------------------------
// Fused attention v8 — 128-thread CTAs (64 queries), 4 CTAs/SM; fp16 PV
// accumulators; f16x2 MUFU exp; ones-column rowsum; cp.async double-buffer.
// ---------------------------------------------------------------------------
__global__ __launch_bounds__(128, 4)
void attn_ptx(const __half* __restrict__ q, const __half* __restrict__ k,
              const __half* __restrict__ v, __half* __restrict__ ctx) {
    extern __shared__ char smraw[];
    __half* Qh = (__half*)smraw;                 // [64][72]     9216 B
    __half* Ks = Qh + 64 * 72;                   // [2][64][72] 18432 B
    __half* Vs = Ks + 2 * 64 * 72;               // [2][64][88] 22528 B

    const int bh  = blockIdx.y;
    const int q0  = blockIdx.x * 64;
    const int tid = threadIdx.x;
    const int wid = tid >> 5;            // 0..3
    const int rw  = wid * 16;
    const int lane = tid & 31;
    const int lrow = lane >> 2;
    const int lcol = lane & 3;

    const __half* qb = q + (size_t)bh * LL * DD;
    const __half* kb = k + (size_t)bh * LL * DD;
    const __half* vb = v + (size_t)bh * LL * DD;

    const int sr = tid >> 3;             // 0..15
    const int sd = (tid & 7) * 8;        // 0..56

    const unsigned scale2 = 0x31C531C5u; // half2(0.18034) = 0.125*log2e

    // ones/zero pad for V cols 64..79 (both buffers): 128 rows, 128 threads
    {
        int buf = tid >> 6, r = tid & 63;
        *(uint4*)&Vs[(buf * 64 + r) * 88 + 64] = make_uint4(0x00003C00u, 0u, 0u, 0u);
        *(uint4*)&Vs[(buf * 64 + r) * 88 + 72] = make_uint4(0u, 0u, 0u, 0u);
    }

    // stage Q (64 rows) + KV tile 0 (64 rows each)
    #pragma unroll
    for (int it = 0; it < 4; it++) {
        int r = it * 16 + sr;
        cp_async16(smem_u32(&Qh[r * 72 + sd]), &qb[(size_t)(q0 + r) * DD + sd]);
    }
    #pragma unroll
    for (int it = 0; it < 4; it++) {
        int r = it * 16 + sr;
        cp_async16(smem_u32(&Ks[r * 72 + sd]), &kb[(size_t)r * DD + sd]);
        cp_async16(smem_u32(&Vs[r * 88 + sd]), &vb[(size_t)r * DD + sd]);
    }
    cp_commit();
    cp_wait0();
    __syncthreads();

    unsigned qa[4][4];
    #pragma unroll
    for (int kg = 0; kg < 4; kg++) {
        unsigned addr = smem_u32(&Qh[(rw + (lane & 15)) * 72 + kg * 16 + (lane >> 4) * 8]);
        ldm_x4(qa[kg][0], qa[kg][1], qa[kg][2], qa[kg][3], addr);
    }

    unsigned oh[8][2];                    // fp16 PV accumulators
    #pragma unroll
    for (int i = 0; i < 8; i++) { oh[i][0] = 0u; oh[i][1] = 0u; }
    unsigned o5[2] = {0u, 0u};            // ones-column accumulator (rowsums)

    const int NT = LL / 64;
    for (int t = 0; t < NT; t++) {
        const int cur = t & 1;
        __half* Kc = Ks + cur * 64 * 72;
        __half* Vc = Vs + cur * 64 * 88;

        if (t + 1 < NT) {
            const int nxt = (t + 1) & 1;
            __half* Kn = Ks + nxt * 64 * 72;
            __half* Vn = Vs + nxt * 64 * 88;
            size_t base = (size_t)(t + 1) * 64 * DD;
            #pragma unroll
            for (int it = 0; it < 4; it++) {
                int r = it * 16 + sr;
                cp_async16(smem_u32(&Kn[r * 72 + sd]), &kb[base + (size_t)r * DD + sd]);
                cp_async16(smem_u32(&Vn[r * 88 + sd]), &vb[base + (size_t)r * DD + sd]);
            }
            cp_commit();
        }

        // ---- S = Q @ K^T (fp16 accum) ----
        unsigned s[8][2];
        #pragma unroll
        for (int nb = 0; nb < 8; nb++) { s[nb][0] = 0u; s[nb][1] = 0u; }
        #pragma unroll
        for (int kg = 0; kg < 4; kg++) {
            #pragma unroll
            for (int nb2 = 0; nb2 < 4; nb2++) {
                unsigned r0, r1, r2, r3;
                unsigned addr = smem_u32(&Kc[(nb2 * 16 + (lane & 15)) * 72 +
                                             kg * 16 + (lane >> 4) * 8]);
                ldm_x4(r0, r1, r2, r3, addr);     // NON-trans: B[k][n]=K[key=n][d=k]
                mma16816_h(s[nb2 * 2][0], s[nb2 * 2][1],
                           qa[kg][0], qa[kg][1], qa[kg][2], qa[kg][3], r0, r2);
                mma16816_h(s[nb2 * 2 + 1][0], s[nb2 * 2 + 1][1],
                           qa[kg][0], qa[kg][1], qa[kg][2], qa[kg][3], r1, r3);
            }
        }

        // ---- P = exp(S/8), packed f16x2 MUFU, in place ----
        #pragma unroll
        for (int nb = 0; nb < 8; nb++) {
            s[nb][0] = exp8_h2(s[nb][0], scale2);
            s[nb][1] = exp8_h2(s[nb][1], scale2);
        }

        // ---- O += P @ V (fp16 accum); rowsum via ones column ----
        #pragma unroll
        for (int kg2 = 0; kg2 < 4; kg2++) {
            unsigned a0 = s[kg2 * 2][0], a1 = s[kg2 * 2][1];
            unsigned a2 = s[kg2 * 2 + 1][0], a3 = s[kg2 * 2 + 1][1];
            #pragma unroll
            for (int db2 = 0; db2 < 4; db2++) {
                unsigned r0, r1, r2, r3;
                unsigned addr = smem_u32(&Vc[(kg2 * 16 + (lane & 15)) * 88 +
                                             db2 * 16 + (lane >> 4) * 8]);
                ldm_x4_t(r0, r1, r2, r3, addr);   // trans: B[k][n]=V[key=k][d=n]
                mma16816_h(oh[db2 * 2][0], oh[db2 * 2][1], a0, a1, a2, a3, r0, r1);
                mma16816_h(oh[db2 * 2 + 1][0], oh[db2 * 2 + 1][1], a0, a1, a2, a3, r2, r3);
            }
            {   // ones block: cols 64-79, keep first 8 cols (col 64 = ones)
                unsigned r0, r1, r2, r3;
                unsigned addr = smem_u32(&Vc[(kg2 * 16 + (lane & 15)) * 88 +
                                             64 + (lane >> 4) * 8]);
                ldm_x4_t(r0, r1, r2, r3, addr);
                mma16816_h(o5[0], o5[1], a0, a1, a2, a3, r0, r1);
            }
        }

        cp_wait0();
        __syncthreads();
    }

    // rowsums: col 64 (block col 0) low half, owned by lcol==0 in the quad
    unsigned u_lo = __shfl_sync(0xffffffffu, o5[0], lane & 28);
    unsigned u_hi = __shfl_sync(0xffffffffu, o5[1], lane & 28);
    float rs_lo = __half2float(__low2half(*(__half2*)&u_lo));
    float rs_hi = __half2float(__low2half(*(__half2*)&u_hi));
    float inv_lo = 1.0f / rs_lo;
    float inv_hi = 1.0f / rs_hi;

    const int b = bh >> 3, h = bh & 7;
    const int row_lo = q0 + rw + lrow;
    __half* dst_lo = ctx + ((size_t)(b * LL + row_lo)) * CC + h * DD + 2 * lcol;
    __half* dst_hi = dst_lo + (size_t)8 * CC;
    #pragma unroll
    for (int db = 0; db < 8; db++) {
        float2 flo = __half22float2(*(__half2*)&oh[db][0]);
        float2 fhi = __half22float2(*(__half2*)&oh[db][1]);
        *(__half2*)&dst_lo[db * 8] = __floats2half2_rn(flo.x * inv_lo, flo.y * inv_lo);
        *(__half2*)&dst_hi[db * 8] = __floats2half2_rn(fhi.x * inv_hi, fhi.y * inv_hi);
    }
}

// ---------------------------------------------------------------------------
// Output GEMM + residual, 128(c) x 128(l) tile, fp16 accumulators (R14).
// ---------------------------------------------------------------------------
__global__ __launch_bounds__(256, 2) void outproj_h(const __half* __restrict__ ctxh,
                                                    const __half* __restrict__ Woh,
                                                    const float* __restrict__ bo,
                                                    const float* __restrict__ ppg,
                                                    float* __restrict__ out) {
    extern __shared__ char smraw[];
    __half* As = (__half*)smraw;           // [2][128][72] (c, k)
    __half* Cs = As + 2 * 128 * 72;        // [2][128][72] (l, k)
    __half* Esh = (__half*)smraw;          // epilogue reuse [128][136] fp16

    const int b  = blockIdx.z;
    const int l0 = blockIdx.x * 128;
    const int c0 = blockIdx.y * 128;
    const int tid = threadIdx.x;
    const int wid = tid >> 5;
    const int wm = wid & 3, wn = wid >> 2;

    const __half* ctxb = ctxh + (size_t)b * LL * CC;

    const int ac = tid >> 3, ak8 = (tid & 7) * 8;

    wmma::fragment<wmma::accumulator, 16, 16, 16, __half> acc[2][4];
    #pragma unroll
    for (int i = 0; i < 2; i++)
        #pragma unroll
        for (int j = 0; j < 4; j++) wmma::fill_fragment(acc[i][j], __float2half(0.0f));

    #pragma unroll
    for (int it = 0; it < 4; it++) {
        int c = it * 32 + ac;
        cp_async16(smem_u32(&As[c * 72 + ak8]), &Woh[(size_t)(c0 + c) * CC + ak8]);
    }
    #pragma unroll
    for (int it = 0; it < 4; it++) {
        int l = it * 32 + ac;
        cp_async16(smem_u32(&Cs[l * 72 + ak8]), &ctxb[(size_t)(l0 + l) * CC + ak8]);
    }
    cp_commit();
    cp_wait0();
    __syncthreads();

    for (int t = 0; t < 8; t++) {
        const int buf = t & 1;
        __half* Ab = As + buf * 128 * 72;
        __half* Cb = Cs + buf * 128 * 72;

        if (t < 7) {
            const int nbuf = buf ^ 1;
            __half* An = As + nbuf * 128 * 72;
            __half* Cn = Cs + nbuf * 128 * 72;
            int k0 = (t + 1) * 64;
            #pragma unroll
            for (int it = 0; it < 4; it++) {
                int c = it * 32 + ac;
                cp_async16(smem_u32(&An[c * 72 + ak8]),
                           &Woh[(size_t)(c0 + c) * CC + k0 + ak8]);
            }
            #pragma unroll
            for (int it = 0; it < 4; it++) {
                int l = it * 32 + ac;
                cp_async16(smem_u32(&Cn[l * 72 + ak8]),
                           &ctxb[(size_t)(l0 + l) * CC + k0 + ak8]);
            }
            cp_commit();
        }

        #pragma unroll
        for (int ks = 0; ks < 4; ks++) {
            wmma::fragment<wmma::matrix_a, 16, 16, 16, __half, wmma::row_major> af[2];
            #pragma unroll
            for (int mt = 0; mt < 2; mt++)
                wmma::load_matrix_sync(af[mt], Ab + (wm * 32 + mt * 16) * 72 + ks * 16, 72);
            #pragma unroll
            for (int nt = 0; nt < 4; nt++) {
                wmma::fragment<wmma::matrix_b, 16, 16, 16, __half, wmma::col_major> bf;
                wmma::load_matrix_sync(bf, Cb + (wn * 64 + nt * 16) * 72 + ks * 16, 72);
                wmma::mma_sync(acc[0][nt], af[0], bf, acc[0][nt]);
                wmma::mma_sync(acc[1][nt], af[1], bf, acc[1][nt]);
            }
        }

        cp_wait0();
        __syncthreads();
    }

    #pragma unroll
    for (int mt = 0; mt < 2; mt++)
        #pragma unroll
        for (int nt = 0; nt < 4; nt++)
            wmma::store_matrix_sync(&Esh[(wm * 32 + mt * 16) * 136 + wn * 64 + nt * 16],
                                    acc[mt][nt], 136, wmma::mem_row_major);
    __syncthreads();

    const int r = tid >> 1, hf = tid & 1;
    const int c = c0 + r;
    float bias = bo[c];
    size_t base = (size_t)b * CC * LL + (size_t)c * LL + l0 + hf * 64;
    const __half* es = &Esh[r * 136 + hf * 64];
    #pragma unroll
    for (int j = 0; j < 64; j += 4) {
        __half2 e01 = *(const __half2*)&es[j];
        __half2 e23 = *(const __half2*)&es[j + 2];
        float2 f01 = __half22float2(e01);
        float2 f23 = __half22float2(e23);
        float4 pv = *(const float4*)&ppg[base + j];
        *(float4*)&out[base + j] = make_float4(f01.x + bias + pv.x, f01.y + bias + pv.y,
                                               f23.x + bias + pv.z, f23.y + bias + pv.w);
    }
}

// ---------------------------------------------------------------------------
extern "C" void kernel_launch(void* const* d_in, const int* in_sizes, int n_in,
                              void* d_out, int out_size) {
    const float* ppg = (const float*)d_in[0];
    const float* ecg = (const float*)d_in[1];
    const float* Wq  = (const float*)d_in[2];
    const float* bq  = (const float*)d_in[3];
    const float* Wk  = (const float*)d_in[4];
    const float* bk  = (const float*)d_in[5];
    const float* Wv  = (const float*)d_in[6];
    const float* bv  = (const float*)d_in[7];
    const float* Wo  = (const float*)d_in[8];
    const float* bo  = (const float*)d_in[9];
    float* out = (float*)d_out;

    __half *pq, *pk, *pv, *pctx, *pppgh, *pecgh, *pwh;
    cudaGetSymbolAddress((void**)&pq,    g_q);
    cudaGetSymbolAddress((void**)&pk,    g_k);
    cudaGetSymbolAddress((void**)&pv,    g_v);
    cudaGetSymbolAddress((void**)&pctx,  g_ctx);
    cudaGetSymbolAddress((void**)&pppgh, g_ppgh);
    cudaGetSymbolAddress((void**)&pecgh, g_ecgh);
    cudaGetSymbolAddress((void**)&pwh,   g_wh);

    const int total4 = 2 * NX4 + 4 * NW4;
    cvt_all<<<(total4 + 255) / 256, 256>>>(ppg, ecg, Wq, Wk, Wv, Wo,
                                           pppgh, pecgh, pwh);

    // merged projections: 128x128 tiles, z = which*BB + b
    int smemP = 2 * 64 * 136 * 2 + 2 * 128 * 72 * 2;   // 71680
    cudaFuncSetAttribute(qkv_proj, cudaFuncAttributeMaxDynamicSharedMemorySize, smemP);
    dim3 gridP(LL / 128, CC / 128, 3 * BB);
    qkv_proj<<<gridP, 256, smemP>>>(pppgh, pecgh, pwh, bq, bk, bv, pq, pk, pv);

    // attention: Qh 9216 + Ks 18432 + Vs 22528 = 50176 B, 128 thr, 4 CTAs/SM
    int smemA = 64 * 72 * 2 + 2 * 64 * 72 * 2 + 2 * 64 * 88 * 2;
    cudaFuncSetAttribute(attn_ptx, cudaFuncAttributeMaxDynamicSharedMemorySize, smemA);
    dim3 gridA(LL / 64, BB * HH);
    attn_ptx<<<gridA, 128, smemA>>>(pq, pk, pv, pctx);

    // output projection: 128x128 tiles
    int smemO = 2 * 128 * 72 * 2 + 2 * 128 * 72 * 2;   // 73728
    cudaFuncSetAttribute(outproj_h, cudaFuncAttributeMaxDynamicSharedMemorySize, smemO);
    dim3 gridO(LL / 128, CC / 128, BB);
    outproj_h<<<gridO, 256, smemO>>>(pctx, pwh + 3 * CC * CC, bo, ppg, out);
}

// round 17
// speedup vs baseline: 1.1121x; 1.0644x over previous
#include <cuda_runtime.h>
#include <cuda_fp16.h>
#include <mma.h>
#include <cstdint>

using namespace nvcuda;

#define BB   4
#define HH   8
#define LL   2048
#define CC   512
#define DD   64

// fp16 scratch (allocation-free rule: __device__ globals)
__device__ __half g_q[BB*HH*LL*DD];
__device__ __half g_k[BB*HH*LL*DD];
__device__ __half g_v[BB*HH*LL*DD];
__device__ __half g_ctx[(size_t)BB*LL*CC];
__device__ __half g_ppgh[(size_t)BB*CC*LL];
__device__ __half g_ecgh[(size_t)BB*CC*LL];
__device__ __half g_wh[4*CC*CC];     // Wq | Wk | Wv | Wo

__device__ __forceinline__ uint2 f4_to_h2x2(float4 v) {
    __half2 a = __floats2half2_rn(v.x, v.y);
    __half2 b = __floats2half2_rn(v.z, v.w);
    uint2 r;
    r.x = *(unsigned int*)&a;
    r.y = *(unsigned int*)&b;
    return r;
}

// packed f16x2: out = 2^(in * scale2)   (exp(s/8) with scale = 0.125*log2e)
__device__ __forceinline__ unsigned exp8_h2(unsigned s, unsigned scale2) {
    unsigned t, y;
    asm("mul.rn.f16x2 %0, %1, %2;" : "=r"(t) : "r"(s), "r"(scale2));
    asm("ex2.approx.f16x2 %0, %1;" : "=r"(y) : "r"(t));
    return y;
}

// ---- PTX wrappers -----------------------------------------------------------
__device__ __forceinline__ unsigned smem_u32(const void* p) {
    return (unsigned)__cvta_generic_to_shared(p);
}
__device__ __forceinline__ void ldm_x4(unsigned& r0, unsigned& r1, unsigned& r2,
                                       unsigned& r3, unsigned addr) {
    asm volatile("ldmatrix.sync.aligned.m8n8.x4.shared.b16 {%0,%1,%2,%3}, [%4];"
                 : "=r"(r0), "=r"(r1), "=r"(r2), "=r"(r3) : "r"(addr));
}
__device__ __forceinline__ void ldm_x4_t(unsigned& r0, unsigned& r1, unsigned& r2,
                                         unsigned& r3, unsigned addr) {
    asm volatile("ldmatrix.sync.aligned.m8n8.x4.trans.shared.b16 {%0,%1,%2,%3}, [%4];"
                 : "=r"(r0), "=r"(r1), "=r"(r2), "=r"(r3) : "r"(addr));
}
__device__ __forceinline__ void mma16816_h(unsigned& c0, unsigned& c1,
                                           unsigned a0, unsigned a1, unsigned a2,
                                           unsigned a3, unsigned b0, unsigned b1) {
    asm volatile("mma.sync.aligned.m16n8k16.row.col.f16.f16.f16.f16 "
                 "{%0,%1}, {%2,%3,%4,%5}, {%6,%7}, {%0,%1};"
                 : "+r"(c0), "+r"(c1)
                 : "r"(a0), "r"(a1), "r"(a2), "r"(a3), "r"(b0), "r"(b1));
}
__device__ __forceinline__ void cp_async16(unsigned dst, const void* src) {
    asm volatile("cp.async.ca.shared.global [%0], [%1], 16;"
                 :: "r"(dst), "l"(src));
}
__device__ __forceinline__ void cp_commit() {
    asm volatile("cp.async.commit_group;");
}
__device__ __forceinline__ void cp_wait0() {
    asm volatile("cp.async.wait_group 0;");
}

// ---------------------------------------------------------------------------
// One fused fp32->fp16 conversion for all 6 tensors.
// ---------------------------------------------------------------------------
#define NX4 (BB*CC*LL/4)
#define NW4 (CC*CC/4)
__global__ void cvt_all(const float* __restrict__ ppg, const float* __restrict__ ecg,
                        const float* __restrict__ Wq, const float* __restrict__ Wk,
                        const float* __restrict__ Wv, const float* __restrict__ Wo,
                        __half* __restrict__ ppgh, __half* __restrict__ ecgh,
                        __half* __restrict__ wh) {
    int i = blockIdx.x * blockDim.x + threadIdx.x;
    const float* src;
    __half* dst;
    int off;
    if (i < NX4)                    { src = ppg; dst = ppgh; off = i; }
    else if (i < 2 * NX4)           { src = ecg; dst = ecgh; off = i - NX4; }
    else {
        int wi = i - 2 * NX4;
        int w = wi / NW4;           // 0..3
        off = wi - w * NW4;
        src = (w == 0) ? Wq : (w == 1) ? Wk : (w == 2) ? Wv : Wo;
        dst = wh + (size_t)w * CC * CC;
    }
    float4 v = ((const float4*)src)[off];
    *(uint2*)&dst[(size_t)off * 4] = f4_to_h2x2(v);
}

// ---------------------------------------------------------------------------
// Merged Q/K/V projection, 128(l) x 128(c) tile, fp16 accumulators (R14).
// ---------------------------------------------------------------------------
__global__ __launch_bounds__(256, 2) void qkv_proj(const __half* __restrict__ ppgh,
                                                   const __half* __restrict__ ecgh,
                                                   const __half* __restrict__ wh,
                                                   const float* __restrict__ bq,
                                                   const float* __restrict__ bk,
                                                   const float* __restrict__ bv,
                                                   __half* __restrict__ oq,
                                                   __half* __restrict__ ok,
                                                   __half* __restrict__ ov) {
    extern __shared__ char smraw[];
    __half* As = (__half*)smraw;           // [2][64][136]  (k, l)
    __half* Ws = As + 2 * 64 * 136;        // [2][128][72]  (c, k)
    __half* Esh = (__half*)smraw;          // epilogue reuse: [128][136] fp16

    const int zz = blockIdx.z;
    const int which = zz >> 2;             // 0=q 1=k 2=v
    const int b = zz & 3;
    const __half* Xh = (which == 0) ? ppgh : ecgh;
    const __half* Wh = wh + (size_t)which * CC * CC;
    const float* bias = (which == 0) ? bq : (which == 1) ? bk : bv;
    __half* out = (which == 0) ? oq : (which == 1) ? ok : ov;

    const int l0 = blockIdx.x * 128;
    const int c0 = blockIdx.y * 128;
    const int tid = threadIdx.x;
    const int wid = tid >> 5;
    const int wm = wid & 3, wn = wid >> 2;

    const __half* Xb = Xh + (size_t)b * CC * LL;

    const int akr = tid >> 4, al8 = (tid & 15) * 8;
    const int wc  = tid >> 3, wk8 = (tid & 7) * 8;

    wmma::fragment<wmma::accumulator, 16, 16, 16, __half> acc[2][4];
    #pragma unroll
    for (int i = 0; i < 2; i++)
        #pragma unroll
        for (int j = 0; j < 4; j++) wmma::fill_fragment(acc[i][j], __float2half(0.0f));

    #pragma unroll
    for (int it = 0; it < 4; it++) {
        int kr = it * 16 + akr;
        cp_async16(smem_u32(&As[kr * 136 + al8]), &Xb[(size_t)kr * LL + l0 + al8]);
    }
    #pragma unroll
    for (int it = 0; it < 4; it++) {
        int c = it * 32 + wc;
        cp_async16(smem_u32(&Ws[c * 72 + wk8]), &Wh[(size_t)(c0 + c) * CC + wk8]);
    }
    cp_commit();
    cp_wait0();
    __syncthreads();

    for (int t = 0; t < 8; t++) {
        const int buf = t & 1;
        __half* Ab = As + buf * 64 * 136;
        __half* Wb = Ws + buf * 128 * 72;

        if (t < 7) {
            const int nbuf = buf ^ 1;
            __half* An = As + nbuf * 64 * 136;
            __half* Wn = Ws + nbuf * 128 * 72;
            int k0 = (t + 1) * 64;
            #pragma unroll
            for (int it = 0; it < 4; it++) {
                int kr = it * 16 + akr;
                cp_async16(smem_u32(&An[kr * 136 + al8]),
                           &Xb[(size_t)(k0 + kr) * LL + l0 + al8]);
            }
            #pragma unroll
            for (int it = 0; it < 4; it++) {
                int c = it * 32 + wc;
                cp_async16(smem_u32(&Wn[c * 72 + wk8]),
                           &Wh[(size_t)(c0 + c) * CC + k0 + wk8]);
            }
            cp_commit();
        }

        #pragma unroll
        for (int ks = 0; ks < 4; ks++) {
            wmma::fragment<wmma::matrix_a, 16, 16, 16, __half, wmma::col_major> af[2];
            #pragma unroll
            for (int mt = 0; mt < 2; mt++)
                wmma::load_matrix_sync(af[mt], Ab + (ks * 16) * 136 + wm * 32 + mt * 16, 136);
            #pragma unroll
            for (int nt = 0; nt < 4; nt++) {
                wmma::fragment<wmma::matrix_b, 16, 16, 16, __half, wmma::col_major> bf;
                wmma::load_matrix_sync(bf, Wb + (wn * 64 + nt * 16) * 72 + ks * 16, 72);
                wmma::mma_sync(acc[0][nt], af[0], bf, acc[0][nt]);
                wmma::mma_sync(acc[1][nt], af[1], bf, acc[1][nt]);
            }
        }

        cp_wait0();
        __syncthreads();
    }

    #pragma unroll
    for (int mt = 0; mt < 2; mt++)
        #pragma unroll
        for (int nt = 0; nt < 4; nt++)
            wmma::store_matrix_sync(&Esh[(wm * 32 + mt * 16) * 136 + wn * 64 + nt * 16],
                                    acc[mt][nt], 136, wmma::mem_row_major);
    __syncthreads();

    const int r = tid >> 1, hf = tid & 1;
    const int h = (c0 >> 6) + hf;
    __half* dst = out + ((size_t)((b * HH + h) * LL) + l0 + r) * DD;
    const __half* es = &Esh[r * 136 + hf * 64];
    const float* bs = &bias[c0 + hf * 64];
    #pragma unroll
    for (int j = 0; j < 64; j += 4) {
        __half2 e01 = *(const __half2*)&es[j];
        __half2 e23 = *(const __half2*)&es[j + 2];
        float2 f01 = __half22float2(e01);
        float2 f23 = __half22float2(e23);
        float4 bv4 = *(const float4*)&bs[j];
        *(uint2*)&dst[j] = f4_to_h2x2(make_float4(f01.x + bv4.x, f01.y + bv4.y,
                                                  f23.x + bv4.z, f23.y + bv4.w));
    }
}

// ---------------------------------------------------------------------------
// Fused attention v9 — 32 queries per warp (2 A-frag halves): each K/V
// B-fragment feeds 4 MMAs instead of 2, halving LDSM bytes per query.
// 128 threads = 128 queries/CTA, 3 CTAs/SM. fp16 accum, f16x2 exp,
// ones-column rowsum, cp.async double-buffer.
// ---------------------------------------------------------------------------
__global__ __launch_bounds__(128, 3)
void attn_ptx(const __half* __restrict__ q, const __half* __restrict__ k,
              const __half* __restrict__ v, __half* __restrict__ ctx) {
    extern __shared__ char smraw[];
    __half* Qh = (__half*)smraw;                 // [128][72]   18432 B
    __half* Ks = Qh + 128 * 72;                  // [2][64][72] 18432 B
    __half* Vs = Ks + 2 * 64 * 72;               // [2][64][88] 22528 B

    const int bh  = blockIdx.y;
    const int q0  = blockIdx.x * 128;
    const int tid = threadIdx.x;
    const int wid = tid >> 5;            // 0..3
    const int rw  = wid * 32;            // 32-query strip
    const int lane = tid & 31;
    const int lrow = lane >> 2;
    const int lcol = lane & 3;

    const __half* qb = q + (size_t)bh * LL * DD;
    const __half* kb = k + (size_t)bh * LL * DD;
    const __half* vb = v + (size_t)bh * LL * DD;

    const int sr = tid >> 3;             // 0..15
    const int sd = (tid & 7) * 8;        // 0..56

    const unsigned scale2 = 0x31C531C5u; // half2(0.18034) = 0.125*log2e

    // ones/zero pad for V cols 64..79 (both buffers): 128 rows, 128 threads
    {
        int buf = tid >> 6, r = tid & 63;
        *(uint4*)&Vs[(buf * 64 + r) * 88 + 64] = make_uint4(0x00003C00u, 0u, 0u, 0u);
        *(uint4*)&Vs[(buf * 64 + r) * 88 + 72] = make_uint4(0u, 0u, 0u, 0u);
    }

    // stage Q (128 rows) + KV tile 0 (64 rows each)
    #pragma unroll
    for (int it = 0; it < 8; it++) {
        int r = it * 16 + sr;
        cp_async16(smem_u32(&Qh[r * 72 + sd]), &qb[(size_t)(q0 + r) * DD + sd]);
    }
    #pragma unroll
    for (int it = 0; it < 4; it++) {
        int r = it * 16 + sr;
        cp_async16(smem_u32(&Ks[r * 72 + sd]), &kb[(size_t)r * DD + sd]);
        cp_async16(smem_u32(&Vs[r * 88 + sd]), &vb[(size_t)r * DD + sd]);
    }
    cp_commit();
    cp_wait0();
    __syncthreads();

    // persistent Q a-frags: [kg][half][4]
    unsigned qa[4][2][4];
    #pragma unroll
    for (int kg = 0; kg < 4; kg++)
        #pragma unroll
        for (int hf = 0; hf < 2; hf++) {
            unsigned addr = smem_u32(&Qh[(rw + hf * 16 + (lane & 15)) * 72 +
                                         kg * 16 + (lane >> 4) * 8]);
            ldm_x4(qa[kg][hf][0], qa[kg][hf][1], qa[kg][hf][2], qa[kg][hf][3], addr);
        }

    unsigned oh[2][8][2];                 // fp16 PV accumulators [half][db][2]
    #pragma unroll
    for (int hf = 0; hf < 2; hf++)
        #pragma unroll
        for (int i = 0; i < 8; i++) { oh[hf][i][0] = 0u; oh[hf][i][1] = 0u; }
    unsigned o5[2][2] = {{0u, 0u}, {0u, 0u}};   // ones-column accumulators

    const int NT = LL / 64;
    for (int t = 0; t < NT; t++) {
        const int cur = t & 1;
        __half* Kc = Ks + cur * 64 * 72;
        __half* Vc = Vs + cur * 64 * 88;

        if (t + 1 < NT) {
            const int nxt = (t + 1) & 1;
            __half* Kn = Ks + nxt * 64 * 72;
            __half* Vn = Vs + nxt * 64 * 88;
            size_t base = (size_t)(t + 1) * 64 * DD;
            #pragma unroll
            for (int it = 0; it < 4; it++) {
                int r = it * 16 + sr;
                cp_async16(smem_u32(&Kn[r * 72 + sd]), &kb[base + (size_t)r * DD + sd]);
                cp_async16(smem_u32(&Vn[r * 88 + sd]), &vb[base + (size_t)r * DD + sd]);
            }
            cp_commit();
        }

        // ---- S = Q @ K^T (fp16 accum), both 16-row halves per B-frag ----
        unsigned s[2][8][2];
        #pragma unroll
        for (int hf = 0; hf < 2; hf++)
            #pragma unroll
            for (int nb = 0; nb < 8; nb++) { s[hf][nb][0] = 0u; s[hf][nb][1] = 0u; }
        #pragma unroll
        for (int kg = 0; kg < 4; kg++) {
            #pragma unroll
            for (int nb2 = 0; nb2 < 4; nb2++) {
                unsigned r0, r1, r2, r3;
                unsigned addr = smem_u32(&Kc[(nb2 * 16 + (lane & 15)) * 72 +
                                             kg * 16 + (lane >> 4) * 8]);
                ldm_x4(r0, r1, r2, r3, addr);     // NON-trans: B[k][n]=K[key=n][d=k]
                #pragma unroll
                for (int hf = 0; hf < 2; hf++) {
                    mma16816_h(s[hf][nb2 * 2][0], s[hf][nb2 * 2][1],
                               qa[kg][hf][0], qa[kg][hf][1], qa[kg][hf][2], qa[kg][hf][3],
                               r0, r2);
                    mma16816_h(s[hf][nb2 * 2 + 1][0], s[hf][nb2 * 2 + 1][1],
                               qa[kg][hf][0], qa[kg][hf][1], qa[kg][hf][2], qa[kg][hf][3],
                               r1, r3);
                }
            }
        }

        // ---- P = exp(S/8), packed f16x2 MUFU, in place ----
        #pragma unroll
        for (int hf = 0; hf < 2; hf++)
            #pragma unroll
            for (int nb = 0; nb < 8; nb++) {
                s[hf][nb][0] = exp8_h2(s[hf][nb][0], scale2);
                s[hf][nb][1] = exp8_h2(s[hf][nb][1], scale2);
            }

        // ---- O += P @ V (fp16 accum); rowsum via ones column ----
        #pragma unroll
        for (int kg2 = 0; kg2 < 4; kg2++) {
            #pragma unroll
            for (int db2 = 0; db2 < 4; db2++) {
                unsigned r0, r1, r2, r3;
                unsigned addr = smem_u32(&Vc[(kg2 * 16 + (lane & 15)) * 88 +
                                             db2 * 16 + (lane >> 4) * 8]);
                ldm_x4_t(r0, r1, r2, r3, addr);   // trans: B[k][n]=V[key=k][d=n]
                #pragma unroll
                for (int hf = 0; hf < 2; hf++) {
                    unsigned a0 = s[hf][kg2 * 2][0], a1 = s[hf][kg2 * 2][1];
                    unsigned a2 = s[hf][kg2 * 2 + 1][0], a3 = s[hf][kg2 * 2 + 1][1];
                    mma16816_h(oh[hf][db2 * 2][0], oh[hf][db2 * 2][1],
                               a0, a1, a2, a3, r0, r1);
                    mma16816_h(oh[hf][db2 * 2 + 1][0], oh[hf][db2 * 2 + 1][1],
                               a0, a1, a2, a3, r2, r3);
                }
            }
            {   // ones block: cols 64-79, keep first 8 cols (col 64 = ones)
                unsigned r0, r1, r2, r3;
                unsigned addr = smem_u32(&Vc[(kg2 * 16 + (lane & 15)) * 88 +
                                             64 + (lane >> 4) * 8]);
                ldm_x4_t(r0, r1, r2, r3, addr);
                #pragma unroll
                for (int hf = 0; hf < 2; hf++) {
                    unsigned a0 = s[hf][kg2 * 2][0], a1 = s[hf][kg2 * 2][1];
                    unsigned a2 = s[hf][kg2 * 2 + 1][0], a3 = s[hf][kg2 * 2 + 1][1];
                    mma16816_h(o5[hf][0], o5[hf][1], a0, a1, a2, a3, r0, r1);
                }
            }
        }

        cp_wait0();
        __syncthreads();
    }

    // ---- epilogue per half: rowsums from ones column, normalize, write ----
    const int b = bh >> 3, h = bh & 7;
    #pragma unroll
    for (int hf = 0; hf < 2; hf++) {
        unsigned u_lo = __shfl_sync(0xffffffffu, o5[hf][0], lane & 28);
        unsigned u_hi = __shfl_sync(0xffffffffu, o5[hf][1], lane & 28);
        float inv_lo = 1.0f / __half2float(__low2half(*(__half2*)&u_lo));
        float inv_hi = 1.0f / __half2float(__low2half(*(__half2*)&u_hi));

        const int row_lo = q0 + rw + hf * 16 + lrow;
        __half* dst_lo = ctx + ((size_t)(b * LL + row_lo)) * CC + h * DD + 2 * lcol;
        __half* dst_hi = dst_lo + (size_t)8 * CC;
        #pragma unroll
        for (int db = 0; db < 8; db++) {
            float2 flo = __half22float2(*(__half2*)&oh[hf][db][0]);
            float2 fhi = __half22float2(*(__half2*)&oh[hf][db][1]);
            *(__half2*)&dst_lo[db * 8] = __floats2half2_rn(flo.x * inv_lo, flo.y * inv_lo);
            *(__half2*)&dst_hi[db * 8] = __floats2half2_rn(fhi.x * inv_hi, fhi.y * inv_hi);
        }
    }
}

// ---------------------------------------------------------------------------
// Output GEMM + residual, 128(c) x 128(l) tile, fp16 accumulators (R14).
// ---------------------------------------------------------------------------
__global__ __launch_bounds__(256, 2) void outproj_h(const __half* __restrict__ ctxh,
                                                    const __half* __restrict__ Woh,
                                                    const float* __restrict__ bo,
                                                    const float* __restrict__ ppg,
                                                    float* __restrict__ out) {
    extern __shared__ char smraw[];
    __half* As = (__half*)smraw;           // [2][128][72] (c, k)
    __half* Cs = As + 2 * 128 * 72;        // [2][128][72] (l, k)
    __half* Esh = (__half*)smraw;          // epilogue reuse [128][136] fp16

    const int b  = blockIdx.z;
    const int l0 = blockIdx.x * 128;
    const int c0 = blockIdx.y * 128;
    const int tid = threadIdx.x;
    const int wid = tid >> 5;
    const int wm = wid & 3, wn = wid >> 2;

    const __half* ctxb = ctxh + (size_t)b * LL * CC;

    const int ac = tid >> 3, ak8 = (tid & 7) * 8;

    wmma::fragment<wmma::accumulator, 16, 16, 16, __half> acc[2][4];
    #pragma unroll
    for (int i = 0; i < 2; i++)
        #pragma unroll
        for (int j = 0; j < 4; j++) wmma::fill_fragment(acc[i][j], __float2half(0.0f));

    #pragma unroll
    for (int it = 0; it < 4; it++) {
        int c = it * 32 + ac;
        cp_async16(smem_u32(&As[c * 72 + ak8]), &Woh[(size_t)(c0 + c) * CC + ak8]);
    }
    #pragma unroll
    for (int it = 0; it < 4; it++) {
        int l = it * 32 + ac;
        cp_async16(smem_u32(&Cs[l * 72 + ak8]), &ctxb[(size_t)(l0 + l) * CC + ak8]);
    }
    cp_commit();
    cp_wait0();
    __syncthreads();

    for (int t = 0; t < 8; t++) {
        const int buf = t & 1;
        __half* Ab = As + buf * 128 * 72;
        __half* Cb = Cs + buf * 128 * 72;

        if (t < 7) {
            const int nbuf = buf ^ 1;
            __half* An = As + nbuf * 128 * 72;
            __half* Cn = Cs + nbuf * 128 * 72;
            int k0 = (t + 1) * 64;
            #pragma unroll
            for (int it = 0; it < 4; it++) {
                int c = it * 32 + ac;
                cp_async16(smem_u32(&An[c * 72 + ak8]),
                           &Woh[(size_t)(c0 + c) * CC + k0 + ak8]);
            }
            #pragma unroll
            for (int it = 0; it < 4; it++) {
                int l = it * 32 + ac;
                cp_async16(smem_u32(&Cn[l * 72 + ak8]),
                           &ctxb[(size_t)(l0 + l) * CC + k0 + ak8]);
            }
            cp_commit();
        }

        #pragma unroll
        for (int ks = 0; ks < 4; ks++) {
            wmma::fragment<wmma::matrix_a, 16, 16, 16, __half, wmma::row_major> af[2];
            #pragma unroll
            for (int mt = 0; mt < 2; mt++)
                wmma::load_matrix_sync(af[mt], Ab + (wm * 32 + mt * 16) * 72 + ks * 16, 72);
            #pragma unroll
            for (int nt = 0; nt < 4; nt++) {
                wmma::fragment<wmma::matrix_b, 16, 16, 16, __half, wmma::col_major> bf;
                wmma::load_matrix_sync(bf, Cb + (wn * 64 + nt * 16) * 72 + ks * 16, 72);
                wmma::mma_sync(acc[0][nt], af[0], bf, acc[0][nt]);
                wmma::mma_sync(acc[1][nt], af[1], bf, acc[1][nt]);
            }
        }

        cp_wait0();
        __syncthreads();
    }

    #pragma unroll
    for (int mt = 0; mt < 2; mt++)
        #pragma unroll
        for (int nt = 0; nt < 4; nt++)
            wmma::store_matrix_sync(&Esh[(wm * 32 + mt * 16) * 136 + wn * 64 + nt * 16],
                                    acc[mt][nt], 136, wmma::mem_row_major);
    __syncthreads();

    const int r = tid >> 1, hf = tid & 1;
    const int c = c0 + r;
    float bias = bo[c];
    size_t base = (size_t)b * CC * LL + (size_t)c * LL + l0 + hf * 64;
    const __half* es = &Esh[r * 136 + hf * 64];
    #pragma unroll
    for (int j = 0; j < 64; j += 4) {
        __half2 e01 = *(const __half2*)&es[j];
        __half2 e23 = *(const __half2*)&es[j + 2];
        float2 f01 = __half22float2(e01);
        float2 f23 = __half22float2(e23);
        float4 pv = *(const float4*)&ppg[base + j];
        *(float4*)&out[base + j] = make_float4(f01.x + bias + pv.x, f01.y + bias + pv.y,
                                               f23.x + bias + pv.z, f23.y + bias + pv.w);
    }
}

// ---------------------------------------------------------------------------
extern "C" void kernel_launch(void* const* d_in, const int* in_sizes, int n_in,
                              void* d_out, int out_size) {
    const float* ppg = (const float*)d_in[0];
    const float* ecg = (const float*)d_in[1];
    const float* Wq  = (const float*)d_in[2];
    const float* bq  = (const float*)d_in[3];
    const float* Wk  = (const float*)d_in[4];
    const float* bk  = (const float*)d_in[5];
    const float* Wv  = (const float*)d_in[6];
    const float* bv  = (const float*)d_in[7];
    const float* Wo  = (const float*)d_in[8];
    const float* bo  = (const float*)d_in[9];
    float* out = (float*)d_out;

    __half *pq, *pk, *pv, *pctx, *pppgh, *pecgh, *pwh;
    cudaGetSymbolAddress((void**)&pq,    g_q);
    cudaGetSymbolAddress((void**)&pk,    g_k);
    cudaGetSymbolAddress((void**)&pv,    g_v);
    cudaGetSymbolAddress((void**)&pctx,  g_ctx);
    cudaGetSymbolAddress((void**)&pppgh, g_ppgh);
    cudaGetSymbolAddress((void**)&pecgh, g_ecgh);
    cudaGetSymbolAddress((void**)&pwh,   g_wh);

    const int total4 = 2 * NX4 + 4 * NW4;
    cvt_all<<<(total4 + 255) / 256, 256>>>(ppg, ecg, Wq, Wk, Wv, Wo,
                                           pppgh, pecgh, pwh);

    // merged projections: 128x128 tiles, z = which*BB + b
    int smemP = 2 * 64 * 136 * 2 + 2 * 128 * 72 * 2;   // 71680
    cudaFuncSetAttribute(qkv_proj, cudaFuncAttributeMaxDynamicSharedMemorySize, smemP);
    dim3 gridP(LL / 128, CC / 128, 3 * BB);
    qkv_proj<<<gridP, 256, smemP>>>(pppgh, pecgh, pwh, bq, bk, bv, pq, pk, pv);

    // attention: Qh 18432 + Ks 18432 + Vs 22528 = 59392 B, 128 thr, 3 CTAs/SM
    int smemA = 128 * 72 * 2 + 2 * 64 * 72 * 2 + 2 * 64 * 88 * 2;
    cudaFuncSetAttribute(attn_ptx, cudaFuncAttributeMaxDynamicSharedMemorySize, smemA);
    dim3 gridA(LL / 128, BB * HH);
    attn_ptx<<<gridA, 128, smemA>>>(pq, pk, pv, pctx);

    // output projection: 128x128 tiles (256 threads — R16's launch typo fixed)
    int smemO = 2 * 128 * 72 * 2 + 2 * 128 * 72 * 2;   // 73728
    cudaFuncSetAttribute(outproj_h, cudaFuncAttributeMaxDynamicSharedMemorySize, smemO);
    dim3 gridO(LL / 128, CC / 128, BB);
    outproj_h<<<gridO, 256, smemO>>>(pctx, pwh + 3 * CC * CC, bo, ppg, out);
}